// round 4
// baseline (speedup 1.0000x reference)
#include <cuda_runtime.h>
#include <math.h>

// Problem constants (fixed shapes)
#define Bb 2
#define Tt 1024
#define Dd 2048
#define Hh 16
#define DH 128
#define MTOT (Bb*Tt)      // 2048
#define DHALF (Dd/2)      // 1024

// ---------------- scratch (static device globals; no allocation) ----------------
__device__ float g_q[Bb*Tt*Dd];       // 16 MB
__device__ float g_l2[Bb*Tt*Dd];      // 16 MB
__device__ float g_fused[Bb*Tt*Dd];   // 16 MB
__device__ float g_hdn[MTOT*DHALF];   // 8 MB
__device__ float g_lam[MTOT*3];
__device__ float g_attn[Bb*Tt*Dd];    // 16 MB

// ---------------- EMA scan: l2[b,t,c] = 0.9*l2[b,t-1,c] + 0.1*x[b,t,c] ----------------
__global__ void ema_kernel(const float* __restrict__ x, float* __restrict__ l2) {
    int i = blockIdx.x * blockDim.x + threadIdx.x;
    if (i >= Bb * Dd) return;
    int b = i / Dd, c = i % Dd;
    const float* xp = x + (size_t)b * Tt * Dd + c;
    float* lp = l2 + (size_t)b * Tt * Dd + c;
    float s = 0.0f;
#pragma unroll 4
    for (int t = 0; t < Tt; t++) {
        s = 0.9f * s + 0.1f * xp[(size_t)t * Dd];
        lp[(size_t)t * Dd] = s;
    }
}

// ---------------- tiled NT SGEMM: C[M,N] = A[M,K] * B[N,K]^T ----------------
// EPI 0: plain store. EPI 1: +bias then SiLU. EPI 2: permute store into [b,h,t,dh].
template <int EPI>
__global__ void __launch_bounds__(256)
gemm_nt(const float* __restrict__ A, const float* __restrict__ Bm,
        const float* __restrict__ bias, float* __restrict__ C,
        int M, int N, int K) {
    __shared__ float As[8][132];
    __shared__ float Bs[8][132];
    const int tid = threadIdx.x;
    const int m0 = blockIdx.y * 128, n0 = blockIdx.x * 128;
    const int lr = tid >> 1;          // 0..127
    const int lk = (tid & 1) * 4;     // 0 or 4
    const float* Ag = A + (size_t)(m0 + lr) * K + lk;
    const float* Bg = Bm + (size_t)(n0 + lr) * K + lk;
    const int ty = tid >> 4, tx = tid & 15;

    float acc[8][8];
#pragma unroll
    for (int i = 0; i < 8; i++)
#pragma unroll
        for (int j = 0; j < 8; j++) acc[i][j] = 0.0f;

    float4 av = *(const float4*)Ag;
    float4 bv = *(const float4*)Bg;

    for (int kk = 0; kk < K; kk += 8) {
        __syncthreads();
        As[lk + 0][lr] = av.x; As[lk + 1][lr] = av.y;
        As[lk + 2][lr] = av.z; As[lk + 3][lr] = av.w;
        Bs[lk + 0][lr] = bv.x; Bs[lk + 1][lr] = bv.y;
        Bs[lk + 2][lr] = bv.z; Bs[lk + 3][lr] = bv.w;
        __syncthreads();
        if (kk + 8 < K) {   // register prefetch of next tile (hides GMEM latency)
            av = *(const float4*)(Ag + kk + 8);
            bv = *(const float4*)(Bg + kk + 8);
        }
#pragma unroll
        for (int k = 0; k < 8; k++) {
            float a[8], b[8];
            *(float4*)(a)     = *(const float4*)&As[k][ty * 8];
            *(float4*)(a + 4) = *(const float4*)&As[k][ty * 8 + 4];
            *(float4*)(b)     = *(const float4*)&Bs[k][tx * 8];
            *(float4*)(b + 4) = *(const float4*)&Bs[k][tx * 8 + 4];
#pragma unroll
            for (int i = 0; i < 8; i++)
#pragma unroll
                for (int j = 0; j < 8; j++)
                    acc[i][j] = fmaf(a[i], b[j], acc[i][j]);
        }
    }

    // epilogue
    float bj[8];
    if (EPI == 1) {
#pragma unroll
        for (int j = 0; j < 8; j++) bj[j] = bias[n0 + tx * 8 + j];
    }
#pragma unroll
    for (int i = 0; i < 8; i++) {
        int m = m0 + ty * 8 + i;
        float r[8];
#pragma unroll
        for (int j = 0; j < 8; j++) {
            float v = acc[i][j];
            if (EPI == 1) {
                v += bj[j];
                v = v / (1.0f + expf(-v));   // SiLU
            }
            r[j] = v;
        }
        float* cp;
        if (EPI == 2) {
            int bb = m >> 10, t = m & 1023;
            int h = n0 >> 7;   // n0 is a multiple of 128, tile spans one head
            cp = C + ((size_t)(bb * Hh + h) * Tt + t) * DH + tx * 8;
        } else {
            cp = C + (size_t)m * N + n0 + tx * 8;
        }
        *(float4*)(cp)     = make_float4(r[0], r[1], r[2], r[3]);
        *(float4*)(cp + 4) = make_float4(r[4], r[5], r[6], r[7]);
    }
}

// ---------------- router head: logits = hdn @ rw2^T + rb2 ; lam = softmax3 ----------------
__global__ void router_kernel(const float* __restrict__ hdn, const float* __restrict__ rw2,
                              const float* __restrict__ rb2, float* __restrict__ lamA,
                              float* __restrict__ lamB) {
    int m = blockIdx.x;
    int tid = threadIdx.x;   // 128 threads
    const float* hp = hdn + (size_t)m * DHALF;
    float p0 = 0.f, p1 = 0.f, p2 = 0.f;
    for (int k = tid; k < DHALF; k += 128) {
        float hv = hp[k];
        p0 = fmaf(hv, rw2[k], p0);
        p1 = fmaf(hv, rw2[DHALF + k], p1);
        p2 = fmaf(hv, rw2[2 * DHALF + k], p2);
    }
#pragma unroll
    for (int off = 16; off; off >>= 1) {
        p0 += __shfl_xor_sync(0xffffffffu, p0, off);
        p1 += __shfl_xor_sync(0xffffffffu, p1, off);
        p2 += __shfl_xor_sync(0xffffffffu, p2, off);
    }
    __shared__ float sb[3][4];
    if ((tid & 31) == 0) {
        int w = tid >> 5;
        sb[0][w] = p0; sb[1][w] = p1; sb[2][w] = p2;
    }
    __syncthreads();
    if (tid == 0) {
        float l0 = sb[0][0] + sb[0][1] + sb[0][2] + sb[0][3] + rb2[0];
        float l1 = sb[1][0] + sb[1][1] + sb[1][2] + sb[1][3] + rb2[1];
        float l2 = sb[2][0] + sb[2][1] + sb[2][2] + sb[2][3] + rb2[2];
        float mx = fmaxf(l0, fmaxf(l1, l2));
        float e0 = expf(l0 - mx), e1 = expf(l1 - mx), e2 = expf(l2 - mx);
        float inv = 1.0f / (e0 + e1 + e2);
        float v0 = e0 * inv, v1 = e1 * inv, v2 = e2 * inv;
        lamA[m * 3 + 0] = v0; lamA[m * 3 + 1] = v1; lamA[m * 3 + 2] = v2;
        lamB[m * 3 + 0] = v0; lamB[m * 3 + 1] = v1; lamB[m * 3 + 2] = v2;
    }
}

// ---------------- fused = lam0*x + lam1*l2 + lam2*l3 ----------------
__global__ void fuse_kernel(const float* __restrict__ x, const float* __restrict__ l2,
                            const float* __restrict__ l3, const float* __restrict__ lam,
                            float* __restrict__ fused) {
    int idx = blockIdx.x * blockDim.x + threadIdx.x;       // float4 index
    if (idx >= Bb * Tt * Dd / 4) return;
    int m = idx / (Dd / 4);
    int c = (idx - m * (Dd / 4)) * 4;
    int b = m >> 10;
    const float* lp = lam + (size_t)m * 3;
    float a0 = lp[0], a1 = lp[1], a2 = lp[2];
    float4 xv = *(const float4*)(x + (size_t)m * Dd + c);
    float4 l2v = *(const float4*)(l2 + (size_t)m * Dd + c);
    float4 l3v = *(const float4*)(l3 + (size_t)b * Dd + c);
    float4 r;
    r.x = a0 * xv.x + a1 * l2v.x + a2 * l3v.x;
    r.y = a0 * xv.y + a1 * l2v.y + a2 * l3v.y;
    r.z = a0 * xv.z + a1 * l2v.z + a2 * l3v.z;
    r.w = a0 * xv.w + a1 * l2v.w + a2 * l3v.w;
    *(float4*)(fused + (size_t)m * Dd + c) = r;
}

// ---------------- flash attention (causal), fp32 ----------------
// Grid: (16 q-blocks of 64 rows, 32 b*h). Block: 256 threads.
// Dynamic smem: Qs/Ks/Vs [64][132] + Ps [64][68].
#define AST 132
#define PST 68
#define ATTN_SMEM ((3 * 64 * AST + 64 * PST) * 4)

__global__ void __launch_bounds__(256)
attn_kernel(const float* __restrict__ q, const float* __restrict__ kh,
            const float* __restrict__ vh, float* __restrict__ aout) {
    extern __shared__ float sm[];
    float* Qs = sm;
    float* Ks = Qs + 64 * AST;
    float* Vs = Ks + 64 * AST;
    float* Ps = Vs + 64 * AST;

    const int tid = threadIdx.x;
    const int qb = blockIdx.x;            // 0..15
    const int bh = blockIdx.y;            // 0..31
    const int b = bh >> 4, h = bh & 15;
    const int q0 = qb * 64;
    const float scale = 0.08838834764831845f;   // 1/sqrt(128)

    // load Q tile (pre-scaled)
    {
        const float* qbase = q + ((size_t)(b * Tt + q0)) * Dd + h * DH;
        for (int f = tid; f < 64 * 32; f += 256) {
            int row = f >> 5, c4 = (f & 31) * 4;
            float4 v = *(const float4*)(qbase + (size_t)row * Dd + c4);
            v.x *= scale; v.y *= scale; v.z *= scale; v.w *= scale;
            *(float4*)&Qs[row * AST + c4] = v;
        }
    }

    const int ty = tid >> 4, tx = tid & 15;
    float m_i[4], l_i[4], oacc[4][8];
#pragma unroll
    for (int i = 0; i < 4; i++) {
        m_i[i] = -1e30f; l_i[i] = 0.0f;
#pragma unroll
        for (int c = 0; c < 8; c++) oacc[i][c] = 0.0f;
    }

    const float* kbase = kh + (size_t)(b * Hh + h) * Tt * DH;
    const float* vbase = vh + (size_t)(b * Hh + h) * Tt * DH;

    for (int jb = 0; jb <= qb; jb++) {
        __syncthreads();   // prior O-GEMM done reading Vs/Ps
        for (int f = tid; f < 64 * 32; f += 256) {
            int row = f >> 5, c4 = (f & 31) * 4;
            *(float4*)&Ks[row * AST + c4] =
                *(const float4*)(kbase + (size_t)(jb * 64 + row) * DH + c4);
            *(float4*)&Vs[row * AST + c4] =
                *(const float4*)(vbase + (size_t)(jb * 64 + row) * DH + c4);
        }
        __syncthreads();

        // S = (Q*scale) @ K^T : 4x4 microtile; cols j*16+tx, rows ty*4+i
        float s[4][4];
#pragma unroll
        for (int i = 0; i < 4; i++)
#pragma unroll
            for (int j = 0; j < 4; j++) s[i][j] = 0.0f;

        for (int k4 = 0; k4 < DH; k4 += 4) {
            float4 a[4], kq[4];
#pragma unroll
            for (int i = 0; i < 4; i++)
                a[i] = *(const float4*)&Qs[(ty * 4 + i) * AST + k4];
#pragma unroll
            for (int j = 0; j < 4; j++)
                kq[j] = *(const float4*)&Ks[(j * 16 + tx) * AST + k4];
#pragma unroll
            for (int i = 0; i < 4; i++)
#pragma unroll
                for (int j = 0; j < 4; j++) {
                    s[i][j] = fmaf(a[i].x, kq[j].x, s[i][j]);
                    s[i][j] = fmaf(a[i].y, kq[j].y, s[i][j]);
                    s[i][j] = fmaf(a[i].z, kq[j].z, s[i][j]);
                    s[i][j] = fmaf(a[i].w, kq[j].w, s[i][j]);
                }
        }

        if (jb == qb) {   // diagonal block: causal mask
#pragma unroll
            for (int i = 0; i < 4; i++)
#pragma unroll
                for (int j = 0; j < 4; j++)
                    if (j * 16 + tx > ty * 4 + i) s[i][j] = -1e30f;
        }

        // online softmax (rows live in 16-lane tx groups within a warp)
#pragma unroll
        for (int i = 0; i < 4; i++) {
            float mx = fmaxf(fmaxf(s[i][0], s[i][1]), fmaxf(s[i][2], s[i][3]));
#pragma unroll
            for (int off = 8; off; off >>= 1)
                mx = fmaxf(mx, __shfl_xor_sync(0xffffffffu, mx, off));
            float mnew = fmaxf(m_i[i], mx);
            float corr = expf(m_i[i] - mnew);
            float rs = 0.0f;
#pragma unroll
            for (int j = 0; j < 4; j++) {
                s[i][j] = expf(s[i][j] - mnew);
                rs += s[i][j];
            }
#pragma unroll
            for (int off = 8; off; off >>= 1)
                rs += __shfl_xor_sync(0xffffffffu, rs, off);
            l_i[i] = l_i[i] * corr + rs;
            m_i[i] = mnew;
#pragma unroll
            for (int c = 0; c < 8; c++) oacc[i][c] *= corr;
#pragma unroll
            for (int j = 0; j < 4; j++)
                Ps[(ty * 4 + i) * PST + j * 16 + tx] = s[i][j];
        }
        __syncthreads();

        // O += P @ V : rows ty*4+i, cols tx*8..+7
        for (int j4 = 0; j4 < 64; j4 += 4) {
            float4 pr[4];
#pragma unroll
            for (int i = 0; i < 4; i++)
                pr[i] = *(const float4*)&Ps[(ty * 4 + i) * PST + j4];
#pragma unroll
            for (int jj = 0; jj < 4; jj++) {
                float4 va = *(const float4*)&Vs[(j4 + jj) * AST + tx * 8];
                float4 vb = *(const float4*)&Vs[(j4 + jj) * AST + tx * 8 + 4];
#pragma unroll
                for (int i = 0; i < 4; i++) {
                    float p = ((const float*)&pr[i])[jj];
                    oacc[i][0] = fmaf(p, va.x, oacc[i][0]);
                    oacc[i][1] = fmaf(p, va.y, oacc[i][1]);
                    oacc[i][2] = fmaf(p, va.z, oacc[i][2]);
                    oacc[i][3] = fmaf(p, va.w, oacc[i][3]);
                    oacc[i][4] = fmaf(p, vb.x, oacc[i][4]);
                    oacc[i][5] = fmaf(p, vb.y, oacc[i][5]);
                    oacc[i][6] = fmaf(p, vb.z, oacc[i][6]);
                    oacc[i][7] = fmaf(p, vb.w, oacc[i][7]);
                }
            }
        }
    }

    // epilogue: write attn output back in [b,t,d] layout for the wo GEMM
#pragma unroll
    for (int i = 0; i < 4; i++) {
        float inv = 1.0f / l_i[i];
        float* op = aout + (size_t)(b * Tt + q0 + ty * 4 + i) * Dd + h * DH + tx * 8;
        *(float4*)(op) = make_float4(oacc[i][0] * inv, oacc[i][1] * inv,
                                     oacc[i][2] * inv, oacc[i][3] * inv);
        *(float4*)(op + 4) = make_float4(oacc[i][4] * inv, oacc[i][5] * inv,
                                         oacc[i][6] * inv, oacc[i][7] * inv);
    }
}

// ---------------- launcher ----------------
extern "C" void kernel_launch(void* const* d_in, const int* in_sizes, int n_in,
                              void* d_out, int out_size) {
    (void)in_sizes; (void)n_in; (void)out_size;
    const float* x   = (const float*)d_in[0];
    const float* l3  = (const float*)d_in[1];
    const float* wq  = (const float*)d_in[2];
    const float* wk  = (const float*)d_in[3];
    const float* wv  = (const float*)d_in[4];
    const float* wo  = (const float*)d_in[5];
    const float* rw1 = (const float*)d_in[6];
    const float* rb1 = (const float*)d_in[7];
    const float* rw2 = (const float*)d_in[8];
    const float* rb2 = (const float*)d_in[9];

    float* out = (float*)d_out;                       // [b,t,d]
    float* kh  = out + (size_t)Bb * Tt * Dd;          // [b,h,t,dh]
    float* vh  = kh + (size_t)Bb * Tt * Dd;           // [b,h,t,dh]
    float* lam = vh + (size_t)Bb * Tt * Dd;           // [b,t,3]

    float *pq, *pl2, *pfused, *phdn, *plam, *pattn;
    cudaGetSymbolAddress((void**)&pq, g_q);
    cudaGetSymbolAddress((void**)&pl2, g_l2);
    cudaGetSymbolAddress((void**)&pfused, g_fused);
    cudaGetSymbolAddress((void**)&phdn, g_hdn);
    cudaGetSymbolAddress((void**)&plam, g_lam);
    cudaGetSymbolAddress((void**)&pattn, g_attn);

    cudaFuncSetAttribute(attn_kernel,
                         cudaFuncAttributeMaxDynamicSharedMemorySize, ATTN_SMEM);

    // 1. EMA scan (independent of GEMMs)
    ema_kernel<<<(Bb * Dd + 127) / 128, 128>>>(x, pl2);
    // 2. q = x @ wq^T
    gemm_nt<0><<<dim3(16, 16), 256>>>(x, wq, nullptr, pq, MTOT, Dd, Dd);
    // 3. hdn = silu(q @ rw1^T + rb1)
    gemm_nt<1><<<dim3(8, 16), 256>>>(pq, rw1, rb1, phdn, MTOT, DHALF, Dd);
    // 4. lam = softmax(hdn @ rw2^T + rb2)  -> scratch + output
    router_kernel<<<MTOT, 128>>>(phdn, rw2, rb2, plam, lam);
    // 5. fused = lam0*x + lam1*l2 + lam2*l3
    fuse_kernel<<<(Bb * Tt * Dd / 4 + 255) / 256, 256>>>(x, pl2, l3, plam, pfused);
    // 6/7. kh = heads(fused @ wk^T), vh = heads(fused @ wv^T)  (permute epilogue -> output)
    gemm_nt<2><<<dim3(16, 16), 256>>>(pfused, wk, nullptr, kh, MTOT, Dd, Dd);
    gemm_nt<2><<<dim3(16, 16), 256>>>(pfused, wv, nullptr, vh, MTOT, Dd, Dd);
    // 8. causal flash attention
    attn_kernel<<<dim3(16, 32), 256, ATTN_SMEM>>>(pq, kh, vh, pattn);
    // 9. out = attn @ wo^T
    gemm_nt<0><<<dim3(16, 16), 256>>>(pattn, wo, nullptr, out, MTOT, Dd, Dd);
}

// round 9
// speedup vs baseline: 2.7175x; 2.7175x over previous
#include <cuda_runtime.h>
#include <cuda_bf16.h>
#include <math.h>
#include <cstdint>

// Problem constants (fixed shapes)
#define Bb 2
#define Tt 1024
#define Dd 2048
#define Hh 16
#define DH 128
#define MTOT (Bb*Tt)      // 2048
#define DHALF (Dd/2)      // 1024

// ================= helpers (baseline PTX only — no 'a'-suffix features) =================
__device__ __forceinline__ uint32_t smem_to_u32(const void* p) {
    uint32_t a;
    asm("{ .reg .u64 t; cvta.to.shared.u64 t, %1; cvt.u32.u64 %0, t; }" : "=r"(a) : "l"(p));
    return a;
}
__device__ __forceinline__ void ldsm4(uint32_t* r, uint32_t addr) {
    asm volatile("ldmatrix.sync.aligned.m8n8.x4.shared.b16 {%0,%1,%2,%3}, [%4];"
        : "=r"(r[0]), "=r"(r[1]), "=r"(r[2]), "=r"(r[3]) : "r"(addr));
}
__device__ __forceinline__ void mma16816(float* c, const uint32_t* a, uint32_t b0, uint32_t b1) {
    asm volatile("mma.sync.aligned.m16n8k16.row.col.f32.bf16.bf16.f32 "
        "{%0,%1,%2,%3}, {%4,%5,%6,%7}, {%8,%9}, {%0,%1,%2,%3};"
        : "+f"(c[0]), "+f"(c[1]), "+f"(c[2]), "+f"(c[3])
        : "r"(a[0]), "r"(a[1]), "r"(a[2]), "r"(a[3]), "r"(b0), "r"(b1));
}
#define CP_ASYNC16(sa, gp) \
    asm volatile("cp.async.cg.shared.global [%0], [%1], 16;" :: "r"(sa), "l"(gp))
#define CP_COMMIT() asm volatile("cp.async.commit_group;" ::: "memory")
#define CP_WAIT1()  asm volatile("cp.async.wait_group 1;" ::: "memory")

// ---------------- scratch (static device globals; no allocation) ----------------
__device__ float g_q[MTOT*Dd];
__device__ float g_l2[MTOT*Dd];
__device__ float g_hdn[MTOT*DHALF];
__device__ float g_lam[MTOT*3];

// bf16 hi/lo split buffers
__device__ __nv_bfloat16 g_xh[MTOT*Dd],   g_xl[MTOT*Dd];
__device__ __nv_bfloat16 g_wqh[Dd*Dd],    g_wql[Dd*Dd];
__device__ __nv_bfloat16 g_wkh[Dd*Dd],    g_wkl[Dd*Dd];
__device__ __nv_bfloat16 g_wvh[Dd*Dd],    g_wvl[Dd*Dd];
__device__ __nv_bfloat16 g_woh[Dd*Dd],    g_wol[Dd*Dd];
__device__ __nv_bfloat16 g_rw1h[DHALF*Dd],g_rw1l[DHALF*Dd];
__device__ __nv_bfloat16 g_qh[MTOT*Dd],   g_ql[MTOT*Dd];
__device__ __nv_bfloat16 g_fh[MTOT*Dd],   g_fl[MTOT*Dd];
__device__ __nv_bfloat16 g_ah[MTOT*Dd],   g_al[MTOT*Dd];

// ---------------- fp32 -> bf16 hi/lo split ----------------
__global__ void split_kernel(const float* __restrict__ s, __nv_bfloat16* __restrict__ hi,
                             __nv_bfloat16* __restrict__ lo, int n4) {
    int i = blockIdx.x * blockDim.x + threadIdx.x;
    if (i >= n4) return;
    float4 v = ((const float4*)s)[i];
    __nv_bfloat16 h0 = __float2bfloat16(v.x), h1 = __float2bfloat16(v.y);
    __nv_bfloat16 h2 = __float2bfloat16(v.z), h3 = __float2bfloat16(v.w);
    __nv_bfloat16 l0 = __float2bfloat16(v.x - __bfloat162float(h0));
    __nv_bfloat16 l1 = __float2bfloat16(v.y - __bfloat162float(h1));
    __nv_bfloat16 l2v = __float2bfloat16(v.z - __bfloat162float(h2));
    __nv_bfloat16 l3v = __float2bfloat16(v.w - __bfloat162float(h3));
    ((__nv_bfloat162*)hi)[2*i]   = __nv_bfloat162(h0, h1);
    ((__nv_bfloat162*)hi)[2*i+1] = __nv_bfloat162(h2, h3);
    ((__nv_bfloat162*)lo)[2*i]   = __nv_bfloat162(l0, l1);
    ((__nv_bfloat162*)lo)[2*i+1] = __nv_bfloat162(l2v, l3v);
}

// ---------------- EMA scan ----------------
__global__ void ema_kernel(const float* __restrict__ x, float* __restrict__ l2) {
    int i = blockIdx.x * blockDim.x + threadIdx.x;
    if (i >= Bb * Dd) return;
    int b = i / Dd, c = i % Dd;
    const float* xp = x + (size_t)b * Tt * Dd + c;
    float* lp = l2 + (size_t)b * Tt * Dd + c;
    float s = 0.0f;
#pragma unroll 4
    for (int t = 0; t < Tt; t++) {
        s = 0.9f * s + 0.1f * xp[(size_t)t * Dd];
        lp[(size_t)t * Dd] = s;
    }
}

// ================= HMMA bf16 hi/lo split GEMM =================
// C[M,N] = A[M,K] * B[N,K]^T, A=Ah+Al, B=Bh+Bl, D = AhBh + AhBl + AlBh (fp32 accum).
// CTA 128x128, BK=32, 8 warps (2x4), warp tile 64x32, double-buffered cp.async.
// EPI 0: plain. 1: +bias,SiLU. 2: head-permute [b,h,t,dh]. 3: fp32 + bf16 hi/lo split.
#define GBK 32
#define GSTR 80                       // smem row stride in bytes (40 bf16) - conflict-free
#define GTILEB (128 * GSTR)           // 10240
#define GSTAGE (4 * GTILEB)           // 40960 (Ah,Al,Bh,Bl)
#define GSMEM  (2 * GSTAGE)           // 81920

template <int EPI>
__global__ void __launch_bounds__(256, 2)
gemm_tc(const __nv_bfloat16* __restrict__ Ah, const __nv_bfloat16* __restrict__ Al,
        const __nv_bfloat16* __restrict__ Bh, const __nv_bfloat16* __restrict__ Bl,
        const float* __restrict__ bias, float* __restrict__ C,
        __nv_bfloat16* __restrict__ Chi, __nv_bfloat16* __restrict__ Clo,
        int N, int K) {
    extern __shared__ char smem[];
    const uint32_t sbase = smem_to_u32(smem);
    const int tid = threadIdx.x;
    const int wid = tid >> 5, lane = tid & 31;
    const int wm = wid >> 2, wn = wid & 3;     // warp grid 2(m) x 4(n)
    const int gid = lane >> 2, tig = lane & 3;
    const int m0 = blockIdx.y * 128, n0 = blockIdx.x * 128;

    const __nv_bfloat16* base[4] = {
        Ah + (size_t)m0 * K, Al + (size_t)m0 * K,
        Bh + (size_t)n0 * K, Bl + (size_t)n0 * K };

    float acc[4][4][4];
#pragma unroll
    for (int mi = 0; mi < 4; mi++)
#pragma unroll
        for (int nj = 0; nj < 4; nj++)
#pragma unroll
            for (int r = 0; r < 4; r++) acc[mi][nj][r] = 0.0f;

    const int NC = K / GBK;

    // chunk loader: 4 tiles x 128 rows x 64B into stage s
#define LOAD_CHUNK(cc, ss) do { \
        int _c = (cc), _s = (ss); \
_Pragma("unroll") \
        for (int it = 0; it < 8; it++) { \
            int idx = tid + it * 256; \
            int tile = idx >> 9, row = (idx >> 2) & 127, ch = idx & 3; \
            const __nv_bfloat16* gp = base[tile] + (size_t)row * K + _c * GBK + ch * 8; \
            uint32_t sa = sbase + _s * GSTAGE + tile * GTILEB + row * GSTR + ch * 16; \
            CP_ASYNC16(sa, gp); \
        } \
    } while (0)

    LOAD_CHUNK(0, 0); CP_COMMIT();
    LOAD_CHUNK(1, 1); CP_COMMIT();

    // ldmatrix lane address components (constant over loop)
    const int lrow = lane & 15;                 // row within 16
    const int lk8  = (lane >> 4) << 3;          // 0 or 8 (k offset)

    for (int c = 0; c < NC; c++) {
        const int s = c & 1;
        CP_WAIT1();
        __syncthreads();
        const uint32_t st = sbase + s * GSTAGE;
#pragma unroll
        for (int k16 = 0; k16 < 2; k16++) {
            const int k0 = k16 * 16;
            // B fragments: two x4 per precision (covers 4 n-tiles of 8)
            uint32_t bh[2][4], bl[2][4];
#pragma unroll
            for (int p = 0; p < 2; p++) {
                int n = wn * 32 + p * 16 + lrow;
                uint32_t ba = st + 2 * GTILEB + n * GSTR + (k0 + lk8) * 2;
                ldsm4(bh[p], ba);
                ldsm4(bl[p], ba + GTILEB);
            }
#pragma unroll
            for (int mi = 0; mi < 4; mi++) {
                int r = wm * 64 + mi * 16 + lrow;
                uint32_t aa = st + r * GSTR + (k0 + lk8) * 2;
                uint32_t ahf[4], alf[4];
                ldsm4(ahf, aa);
                ldsm4(alf, aa + GTILEB);
#pragma unroll
                for (int nj = 0; nj < 4; nj++) {
                    const int p = nj >> 1, q = nj & 1;
                    mma16816(acc[mi][nj], ahf, bh[p][q], bh[p][q + 2]);
                    mma16816(acc[mi][nj], ahf, bl[p][q], bl[p][q + 2]);
                    mma16816(acc[mi][nj], alf, bh[p][q], bh[p][q + 2]);
                }
            }
        }
        __syncthreads();
        if (c + 2 < NC) LOAD_CHUNK(c + 2, s);
        CP_COMMIT();
    }
#undef LOAD_CHUNK

    // -------- epilogue --------
#pragma unroll
    for (int mi = 0; mi < 4; mi++) {
#pragma unroll
        for (int nj = 0; nj < 4; nj++) {
            const int colw = wn * 32 + nj * 8 + tig * 2;   // col within 128-tile
#pragma unroll
            for (int half = 0; half < 2; half++) {
                const int m = m0 + wm * 64 + mi * 16 + gid + half * 8;
                float v0 = acc[mi][nj][half * 2 + 0];
                float v1 = acc[mi][nj][half * 2 + 1];
                if (EPI == 1) {
                    v0 += bias[n0 + colw];
                    v1 += bias[n0 + colw + 1];
                    v0 = v0 / (1.0f + __expf(-v0));
                    v1 = v1 / (1.0f + __expf(-v1));
                }
                if (EPI == 2) {
                    const int bb = m >> 10, t = m & 1023, h = n0 >> 7;
                    float* cp = C + ((size_t)(bb * Hh + h) * Tt + t) * DH + colw;
                    *(float2*)cp = make_float2(v0, v1);
                } else {
                    float* cp = C + (size_t)m * N + n0 + colw;
                    *(float2*)cp = make_float2(v0, v1);
                }
                if (EPI == 3) {
                    __nv_bfloat16 h0 = __float2bfloat16(v0);
                    __nv_bfloat16 h1 = __float2bfloat16(v1);
                    size_t off = (size_t)m * N + n0 + colw;
                    *(__nv_bfloat162*)(Chi + off) = __nv_bfloat162(h0, h1);
                    *(__nv_bfloat162*)(Clo + off) = __nv_bfloat162(
                        __float2bfloat16(v0 - __bfloat162float(h0)),
                        __float2bfloat16(v1 - __bfloat162float(h1)));
                }
            }
        }
    }
}

// ---------------- router head ----------------
__global__ void router_kernel(const float* __restrict__ hdn, const float* __restrict__ rw2,
                              const float* __restrict__ rb2, float* __restrict__ lamA,
                              float* __restrict__ lamB) {
    int m = blockIdx.x;
    int tid = threadIdx.x;   // 128 threads
    const float* hp = hdn + (size_t)m * DHALF;
    float p0 = 0.f, p1 = 0.f, p2 = 0.f;
    for (int k = tid; k < DHALF; k += 128) {
        float hv = hp[k];
        p0 = fmaf(hv, rw2[k], p0);
        p1 = fmaf(hv, rw2[DHALF + k], p1);
        p2 = fmaf(hv, rw2[2 * DHALF + k], p2);
    }
#pragma unroll
    for (int off = 16; off; off >>= 1) {
        p0 += __shfl_xor_sync(0xffffffffu, p0, off);
        p1 += __shfl_xor_sync(0xffffffffu, p1, off);
        p2 += __shfl_xor_sync(0xffffffffu, p2, off);
    }
    __shared__ float sbm[3][4];
    if ((tid & 31) == 0) {
        int w = tid >> 5;
        sbm[0][w] = p0; sbm[1][w] = p1; sbm[2][w] = p2;
    }
    __syncthreads();
    if (tid == 0) {
        float l0 = sbm[0][0] + sbm[0][1] + sbm[0][2] + sbm[0][3] + rb2[0];
        float l1 = sbm[1][0] + sbm[1][1] + sbm[1][2] + sbm[1][3] + rb2[1];
        float l2 = sbm[2][0] + sbm[2][1] + sbm[2][2] + sbm[2][3] + rb2[2];
        float mx = fmaxf(l0, fmaxf(l1, l2));
        float e0 = __expf(l0 - mx), e1 = __expf(l1 - mx), e2 = __expf(l2 - mx);
        float inv = 1.0f / (e0 + e1 + e2);
        float v0 = e0 * inv, v1 = e1 * inv, v2 = e2 * inv;
        lamA[m * 3 + 0] = v0; lamA[m * 3 + 1] = v1; lamA[m * 3 + 2] = v2;
        lamB[m * 3 + 0] = v0; lamB[m * 3 + 1] = v1; lamB[m * 3 + 2] = v2;
    }
}

// ---------------- fused = lam0*x + lam1*l2 + lam2*l3, emitted as bf16 hi/lo ----------------
__global__ void fuse_kernel(const float* __restrict__ x, const float* __restrict__ l2,
                            const float* __restrict__ l3, const float* __restrict__ lam,
                            __nv_bfloat16* __restrict__ fh, __nv_bfloat16* __restrict__ fl) {
    int idx = blockIdx.x * blockDim.x + threadIdx.x;
    if (idx >= Bb * Tt * Dd / 4) return;
    int m = idx / (Dd / 4);
    int c = (idx - m * (Dd / 4)) * 4;
    int b = m >> 10;
    const float* lp = lam + (size_t)m * 3;
    float a0 = lp[0], a1 = lp[1], a2 = lp[2];
    float4 xv = *(const float4*)(x + (size_t)m * Dd + c);
    float4 l2v = *(const float4*)(l2 + (size_t)m * Dd + c);
    float4 l3v = *(const float4*)(l3 + (size_t)b * Dd + c);
    float r0 = a0 * xv.x + a1 * l2v.x + a2 * l3v.x;
    float r1 = a0 * xv.y + a1 * l2v.y + a2 * l3v.y;
    float r2 = a0 * xv.z + a1 * l2v.z + a2 * l3v.z;
    float r3 = a0 * xv.w + a1 * l2v.w + a2 * l3v.w;
    __nv_bfloat16 h0 = __float2bfloat16(r0), h1 = __float2bfloat16(r1);
    __nv_bfloat16 h2 = __float2bfloat16(r2), h3 = __float2bfloat16(r3);
    size_t off = (size_t)m * Dd + c;
    ((__nv_bfloat162*)(fh + off))[0] = __nv_bfloat162(h0, h1);
    ((__nv_bfloat162*)(fh + off))[1] = __nv_bfloat162(h2, h3);
    ((__nv_bfloat162*)(fl + off))[0] = __nv_bfloat162(
        __float2bfloat16(r0 - __bfloat162float(h0)), __float2bfloat16(r1 - __bfloat162float(h1)));
    ((__nv_bfloat162*)(fl + off))[1] = __nv_bfloat162(
        __float2bfloat16(r2 - __bfloat162float(h2)), __float2bfloat16(r3 - __bfloat162float(h3)));
}

// ---------------- flash attention (causal), fp32; epilogue emits bf16 hi/lo ----------------
#define AST 132
#define PST 68
#define ATTN_SMEM ((3 * 64 * AST + 64 * PST) * 4)

__global__ void __launch_bounds__(256)
attn_kernel(const float* __restrict__ q, const float* __restrict__ kh,
            const float* __restrict__ vh, __nv_bfloat16* __restrict__ ah,
            __nv_bfloat16* __restrict__ al) {
    extern __shared__ float sm[];
    float* Qs = sm;
    float* Ks = Qs + 64 * AST;
    float* Vs = Ks + 64 * AST;
    float* Ps = Vs + 64 * AST;

    const int tid = threadIdx.x;
    const int qb = blockIdx.x;
    const int bh = blockIdx.y;
    const int b = bh >> 4, h = bh & 15;
    const int q0 = qb * 64;
    const float scale = 0.08838834764831845f;

    {
        const float* qbase = q + ((size_t)(b * Tt + q0)) * Dd + h * DH;
        for (int f = tid; f < 64 * 32; f += 256) {
            int row = f >> 5, c4 = (f & 31) * 4;
            float4 v = *(const float4*)(qbase + (size_t)row * Dd + c4);
            v.x *= scale; v.y *= scale; v.z *= scale; v.w *= scale;
            *(float4*)&Qs[row * AST + c4] = v;
        }
    }

    const int ty = tid >> 4, tx = tid & 15;
    float m_i[4], l_i[4], oacc[4][8];
#pragma unroll
    for (int i = 0; i < 4; i++) {
        m_i[i] = -1e30f; l_i[i] = 0.0f;
#pragma unroll
        for (int c = 0; c < 8; c++) oacc[i][c] = 0.0f;
    }

    const float* kbase = kh + (size_t)(b * Hh + h) * Tt * DH;
    const float* vbase = vh + (size_t)(b * Hh + h) * Tt * DH;

    for (int jb = 0; jb <= qb; jb++) {
        __syncthreads();
        for (int f = tid; f < 64 * 32; f += 256) {
            int row = f >> 5, c4 = (f & 31) * 4;
            *(float4*)&Ks[row * AST + c4] =
                *(const float4*)(kbase + (size_t)(jb * 64 + row) * DH + c4);
            *(float4*)&Vs[row * AST + c4] =
                *(const float4*)(vbase + (size_t)(jb * 64 + row) * DH + c4);
        }
        __syncthreads();

        float s[4][4];
#pragma unroll
        for (int i = 0; i < 4; i++)
#pragma unroll
            for (int j = 0; j < 4; j++) s[i][j] = 0.0f;

        for (int k4 = 0; k4 < DH; k4 += 4) {
            float4 a[4], kq[4];
#pragma unroll
            for (int i = 0; i < 4; i++)
                a[i] = *(const float4*)&Qs[(ty * 4 + i) * AST + k4];
#pragma unroll
            for (int j = 0; j < 4; j++)
                kq[j] = *(const float4*)&Ks[(j * 16 + tx) * AST + k4];
#pragma unroll
            for (int i = 0; i < 4; i++)
#pragma unroll
                for (int j = 0; j < 4; j++) {
                    s[i][j] = fmaf(a[i].x, kq[j].x, s[i][j]);
                    s[i][j] = fmaf(a[i].y, kq[j].y, s[i][j]);
                    s[i][j] = fmaf(a[i].z, kq[j].z, s[i][j]);
                    s[i][j] = fmaf(a[i].w, kq[j].w, s[i][j]);
                }
        }

        if (jb == qb) {
#pragma unroll
            for (int i = 0; i < 4; i++)
#pragma unroll
                for (int j = 0; j < 4; j++)
                    if (j * 16 + tx > ty * 4 + i) s[i][j] = -1e30f;
        }

#pragma unroll
        for (int i = 0; i < 4; i++) {
            float mx = fmaxf(fmaxf(s[i][0], s[i][1]), fmaxf(s[i][2], s[i][3]));
#pragma unroll
            for (int off = 8; off; off >>= 1)
                mx = fmaxf(mx, __shfl_xor_sync(0xffffffffu, mx, off));
            float mnew = fmaxf(m_i[i], mx);
            float corr = __expf(m_i[i] - mnew);
            float rs = 0.0f;
#pragma unroll
            for (int j = 0; j < 4; j++) {
                s[i][j] = __expf(s[i][j] - mnew);
                rs += s[i][j];
            }
#pragma unroll
            for (int off = 8; off; off >>= 1)
                rs += __shfl_xor_sync(0xffffffffu, rs, off);
            l_i[i] = l_i[i] * corr + rs;
            m_i[i] = mnew;
#pragma unroll
            for (int c = 0; c < 8; c++) oacc[i][c] *= corr;
#pragma unroll
            for (int j = 0; j < 4; j++)
                Ps[(ty * 4 + i) * PST + j * 16 + tx] = s[i][j];
        }
        __syncthreads();

        for (int j4 = 0; j4 < 64; j4 += 4) {
            float4 pr[4];
#pragma unroll
            for (int i = 0; i < 4; i++)
                pr[i] = *(const float4*)&Ps[(ty * 4 + i) * PST + j4];
#pragma unroll
            for (int jj = 0; jj < 4; jj++) {
                float4 va = *(const float4*)&Vs[(j4 + jj) * AST + tx * 8];
                float4 vb = *(const float4*)&Vs[(j4 + jj) * AST + tx * 8 + 4];
#pragma unroll
                for (int i = 0; i < 4; i++) {
                    float p = ((const float*)&pr[i])[jj];
                    oacc[i][0] = fmaf(p, va.x, oacc[i][0]);
                    oacc[i][1] = fmaf(p, va.y, oacc[i][1]);
                    oacc[i][2] = fmaf(p, va.z, oacc[i][2]);
                    oacc[i][3] = fmaf(p, va.w, oacc[i][3]);
                    oacc[i][4] = fmaf(p, vb.x, oacc[i][4]);
                    oacc[i][5] = fmaf(p, vb.y, oacc[i][5]);
                    oacc[i][6] = fmaf(p, vb.z, oacc[i][6]);
                    oacc[i][7] = fmaf(p, vb.w, oacc[i][7]);
                }
            }
        }
    }

    // epilogue: write bf16 hi/lo splits directly (feeds wo GEMM)
#pragma unroll
    for (int i = 0; i < 4; i++) {
        float inv = 1.0f / l_i[i];
        size_t off = (size_t)(b * Tt + q0 + ty * 4 + i) * Dd + h * DH + tx * 8;
#pragma unroll
        for (int c2 = 0; c2 < 4; c2++) {
            float u0 = oacc[i][c2 * 2 + 0] * inv;
            float u1 = oacc[i][c2 * 2 + 1] * inv;
            __nv_bfloat16 h0 = __float2bfloat16(u0);
            __nv_bfloat16 h1 = __float2bfloat16(u1);
            ((__nv_bfloat162*)(ah + off))[c2] = __nv_bfloat162(h0, h1);
            ((__nv_bfloat162*)(al + off))[c2] = __nv_bfloat162(
                __float2bfloat16(u0 - __bfloat162float(h0)),
                __float2bfloat16(u1 - __bfloat162float(h1)));
        }
    }
}

// ---------------- launcher ----------------
extern "C" void kernel_launch(void* const* d_in, const int* in_sizes, int n_in,
                              void* d_out, int out_size) {
    (void)in_sizes; (void)n_in; (void)out_size;
    const float* x   = (const float*)d_in[0];
    const float* l3  = (const float*)d_in[1];
    const float* wq  = (const float*)d_in[2];
    const float* wk  = (const float*)d_in[3];
    const float* wv  = (const float*)d_in[4];
    const float* wo  = (const float*)d_in[5];
    const float* rw1 = (const float*)d_in[6];
    const float* rb1 = (const float*)d_in[7];
    const float* rw2 = (const float*)d_in[8];
    const float* rb2 = (const float*)d_in[9];

    float* out = (float*)d_out;                       // [b,t,d]
    float* kh  = out + (size_t)Bb * Tt * Dd;          // [b,h,t,dh]
    float* vh  = kh + (size_t)Bb * Tt * Dd;           // [b,h,t,dh]
    float* lam = vh + (size_t)Bb * Tt * Dd;           // [b,t,3]

    float *pq, *pl2, *phdn, *plam;
    cudaGetSymbolAddress((void**)&pq, g_q);
    cudaGetSymbolAddress((void**)&pl2, g_l2);
    cudaGetSymbolAddress((void**)&phdn, g_hdn);
    cudaGetSymbolAddress((void**)&plam, g_lam);

    __nv_bfloat16 *xh,*xl,*wqh,*wql,*wkh,*wkl,*wvh,*wvl,*woh,*wol,*rw1h,*rw1l;
    __nv_bfloat16 *qh,*ql,*fh,*fl,*ah,*al;
    cudaGetSymbolAddress((void**)&xh, g_xh);   cudaGetSymbolAddress((void**)&xl, g_xl);
    cudaGetSymbolAddress((void**)&wqh, g_wqh); cudaGetSymbolAddress((void**)&wql, g_wql);
    cudaGetSymbolAddress((void**)&wkh, g_wkh); cudaGetSymbolAddress((void**)&wkl, g_wkl);
    cudaGetSymbolAddress((void**)&wvh, g_wvh); cudaGetSymbolAddress((void**)&wvl, g_wvl);
    cudaGetSymbolAddress((void**)&woh, g_woh); cudaGetSymbolAddress((void**)&wol, g_wol);
    cudaGetSymbolAddress((void**)&rw1h, g_rw1h); cudaGetSymbolAddress((void**)&rw1l, g_rw1l);
    cudaGetSymbolAddress((void**)&qh, g_qh);   cudaGetSymbolAddress((void**)&ql, g_ql);
    cudaGetSymbolAddress((void**)&fh, g_fh);   cudaGetSymbolAddress((void**)&fl, g_fl);
    cudaGetSymbolAddress((void**)&ah, g_ah);   cudaGetSymbolAddress((void**)&al, g_al);

    cudaFuncSetAttribute(attn_kernel, cudaFuncAttributeMaxDynamicSharedMemorySize, ATTN_SMEM);
    cudaFuncSetAttribute(gemm_tc<0>, cudaFuncAttributeMaxDynamicSharedMemorySize, GSMEM);
    cudaFuncSetAttribute(gemm_tc<1>, cudaFuncAttributeMaxDynamicSharedMemorySize, GSMEM);
    cudaFuncSetAttribute(gemm_tc<2>, cudaFuncAttributeMaxDynamicSharedMemorySize, GSMEM);
    cudaFuncSetAttribute(gemm_tc<3>, cudaFuncAttributeMaxDynamicSharedMemorySize, GSMEM);

    const int NBIG4 = (MTOT * Dd) / 4;
    // 1. EMA scan
    ema_kernel<<<(Bb * Dd + 127) / 128, 128>>>(x, pl2);
    // 2. splits of input/weights
    split_kernel<<<(NBIG4 + 255) / 256, 256>>>(x, xh, xl, NBIG4);
    split_kernel<<<(NBIG4 + 255) / 256, 256>>>(wq, wqh, wql, NBIG4);
    split_kernel<<<(NBIG4 + 255) / 256, 256>>>(wk, wkh, wkl, NBIG4);
    split_kernel<<<(NBIG4 + 255) / 256, 256>>>(wv, wvh, wvl, NBIG4);
    split_kernel<<<(NBIG4 + 255) / 256, 256>>>(wo, woh, wol, NBIG4);
    split_kernel<<<(NBIG4 / 2 + 255) / 256, 256>>>(rw1, rw1h, rw1l, NBIG4 / 2);
    // 3. q = x @ wq^T  (HMMA, fp32 out + bf16 split out)
    gemm_tc<3><<<dim3(16, 16), 256, GSMEM>>>(xh, xl, wqh, wql, nullptr, pq, qh, ql, Dd, Dd);
    // 4. hdn = silu(q @ rw1^T + rb1)
    gemm_tc<1><<<dim3(8, 16), 256, GSMEM>>>(qh, ql, rw1h, rw1l, rb1, phdn, nullptr, nullptr, DHALF, Dd);
    // 5. lam = softmax(hdn @ rw2^T + rb2)
    router_kernel<<<MTOT, 128>>>(phdn, rw2, rb2, plam, lam);
    // 6. fused mix -> bf16 splits directly
    fuse_kernel<<<(Bb * Tt * Dd / 4 + 255) / 256, 256>>>(x, pl2, l3, plam, fh, fl);
    // 7. kh/vh = heads(fused @ w^T)   (HMMA, permute epilogue -> outputs)
    gemm_tc<2><<<dim3(16, 16), 256, GSMEM>>>(fh, fl, wkh, wkl, nullptr, kh, nullptr, nullptr, Dd, Dd);
    gemm_tc<2><<<dim3(16, 16), 256, GSMEM>>>(fh, fl, wvh, wvl, nullptr, vh, nullptr, nullptr, Dd, Dd);
    // 8. causal flash attention (fp32) -> bf16 split output
    attn_kernel<<<dim3(16, 32), 256, ATTN_SMEM>>>(pq, kh, vh, ah, al);
    // 9. out = attn @ wo^T  (HMMA)
    gemm_tc<0><<<dim3(16, 16), 256, GSMEM>>>(ah, al, woh, wol, nullptr, out, nullptr, nullptr, Dd, Dd);
}

// round 10
// speedup vs baseline: 3.6327x; 1.3368x over previous
#include <cuda_runtime.h>
#include <cuda_bf16.h>
#include <math.h>
#include <cstdint>

// Problem constants (fixed shapes)
#define Bb 2
#define Tt 1024
#define Dd 2048
#define Hh 16
#define DH 128
#define MTOT (Bb*Tt)      // 2048
#define DHALF (Dd/2)      // 1024

// ================= helpers (baseline PTX only — no 'a'-suffix features) =================
__device__ __forceinline__ uint32_t smem_to_u32(const void* p) {
    uint32_t a;
    asm("{ .reg .u64 t; cvta.to.shared.u64 t, %1; cvt.u32.u64 %0, t; }" : "=r"(a) : "l"(p));
    return a;
}
__device__ __forceinline__ void ldsm4(uint32_t* r, uint32_t addr) {
    asm volatile("ldmatrix.sync.aligned.m8n8.x4.shared.b16 {%0,%1,%2,%3}, [%4];"
        : "=r"(r[0]), "=r"(r[1]), "=r"(r[2]), "=r"(r[3]) : "r"(addr));
}
__device__ __forceinline__ void ldsm4t(uint32_t* r, uint32_t addr) {
    asm volatile("ldmatrix.sync.aligned.m8n8.x4.trans.shared.b16 {%0,%1,%2,%3}, [%4];"
        : "=r"(r[0]), "=r"(r[1]), "=r"(r[2]), "=r"(r[3]) : "r"(addr));
}
__device__ __forceinline__ void mma16816(float* c, const uint32_t* a, uint32_t b0, uint32_t b1) {
    asm volatile("mma.sync.aligned.m16n8k16.row.col.f32.bf16.bf16.f32 "
        "{%0,%1,%2,%3}, {%4,%5,%6,%7}, {%8,%9}, {%0,%1,%2,%3};"
        : "+f"(c[0]), "+f"(c[1]), "+f"(c[2]), "+f"(c[3])
        : "r"(a[0]), "r"(a[1]), "r"(a[2]), "r"(a[3]), "r"(b0), "r"(b1));
}
#define CP_ASYNC16(sa, gp) \
    asm volatile("cp.async.cg.shared.global [%0], [%1], 16;" :: "r"(sa), "l"(gp))
#define CP_COMMIT() asm volatile("cp.async.commit_group;" ::: "memory")
#define CP_WAIT1()  asm volatile("cp.async.wait_group 1;" ::: "memory")
#define CP_WAIT0()  asm volatile("cp.async.wait_group 0;" ::: "memory")

// ---------------- scratch (static device globals; no allocation) ----------------
__device__ float g_l2[MTOT*Dd];
__device__ float g_hdn[MTOT*DHALF];
__device__ float g_lam[MTOT*3];

// bf16 hi/lo split buffers
__device__ __nv_bfloat16 g_xh[MTOT*Dd],   g_xl[MTOT*Dd];
__device__ __nv_bfloat16 g_wqh[Dd*Dd],    g_wql[Dd*Dd];
__device__ __nv_bfloat16 g_wkh[Dd*Dd],    g_wkl[Dd*Dd];
__device__ __nv_bfloat16 g_wvh[Dd*Dd],    g_wvl[Dd*Dd];
__device__ __nv_bfloat16 g_woh[Dd*Dd],    g_wol[Dd*Dd];
__device__ __nv_bfloat16 g_rw1h[DHALF*Dd],g_rw1l[DHALF*Dd];
__device__ __nv_bfloat16 g_qh[MTOT*Dd],   g_ql[MTOT*Dd];
__device__ __nv_bfloat16 g_fh[MTOT*Dd],   g_fl[MTOT*Dd];
__device__ __nv_bfloat16 g_ah[MTOT*Dd],   g_al[MTOT*Dd];
__device__ __nv_bfloat16 g_khh[MTOT*Dd],  g_khl[MTOT*Dd];   // [b,h,t,dh] splits
__device__ __nv_bfloat16 g_vhh[MTOT*Dd],  g_vhl[MTOT*Dd];

// ---------------- fp32 -> bf16 hi/lo split (generic) ----------------
__device__ __forceinline__ void split2(float a, float b, __nv_bfloat162* hi, __nv_bfloat162* lo) {
    __nv_bfloat16 h0 = __float2bfloat16(a), h1 = __float2bfloat16(b);
    *hi = __nv_bfloat162(h0, h1);
    *lo = __nv_bfloat162(__float2bfloat16(a - __bfloat162float(h0)),
                         __float2bfloat16(b - __bfloat162float(h1)));
}

__global__ void split_kernel(const float* __restrict__ s, __nv_bfloat16* __restrict__ hi,
                             __nv_bfloat16* __restrict__ lo, int n4) {
    int i = blockIdx.x * blockDim.x + threadIdx.x;
    if (i >= n4) return;
    float4 v = ((const float4*)s)[i];
    split2(v.x, v.y, (__nv_bfloat162*)hi + 2*i,     (__nv_bfloat162*)lo + 2*i);
    split2(v.z, v.w, (__nv_bfloat162*)hi + 2*i + 1, (__nv_bfloat162*)lo + 2*i + 1);
}

// 4 equally-sized weight splits in one launch (blockIdx.y selects matrix)
struct SplitArgs { const float* s[4]; __nv_bfloat16* h[4]; __nv_bfloat16* l[4]; };
__global__ void split4_kernel(SplitArgs args, int n4) {
    int i = blockIdx.x * blockDim.x + threadIdx.x;
    if (i >= n4) return;
    int z = blockIdx.y;
    float4 v = ((const float4*)args.s[z])[i];
    split2(v.x, v.y, (__nv_bfloat162*)args.h[z] + 2*i,     (__nv_bfloat162*)args.l[z] + 2*i);
    split2(v.z, v.w, (__nv_bfloat162*)args.h[z] + 2*i + 1, (__nv_bfloat162*)args.l[z] + 2*i + 1);
}

// ---------------- parallel chunked EMA scan + fused x split ----------------
// block = (16 channels) x (16 chunks of 64 steps); grid = Bb * (Dd/16)
__global__ void __launch_bounds__(256)
ema_kernel(const float* __restrict__ x, float* __restrict__ l2,
           __nv_bfloat16* __restrict__ xh, __nv_bfloat16* __restrict__ xl) {
    const float P64 = 0.0011790184577738583f;   // 0.9^64
    int tid = threadIdx.x;
    int ci = tid & 15, k = tid >> 4;
    int b = blockIdx.x >> 7;                    // 128 blocks per batch
    int c = ((blockIdx.x & 127) << 4) + ci;
    const float* xp = x + (size_t)b * Tt * Dd + c;
    float* lp = l2 + (size_t)b * Tt * Dd + c;
    __nv_bfloat16* xhp = xh + (size_t)b * Tt * Dd + c;
    __nv_bfloat16* xlp = xl + (size_t)b * Tt * Dd + c;
    const int t0 = k * 64;

    // phase 1: local scan (endpoint only)
    float s = 0.0f;
#pragma unroll 4
    for (int i = 0; i < 64; i++)
        s = 0.9f * s + 0.1f * xp[(size_t)(t0 + i) * Dd];

    __shared__ float endv[16][17], car[16][17];
    endv[k][ci] = s;
    __syncthreads();
    if (k == 0) {   // phase 2: serial carry over 16 chunks
        float carry = 0.0f;
#pragma unroll
        for (int kk = 0; kk < 16; kk++) {
            car[kk][ci] = carry;
            carry = P64 * carry + endv[kk][ci];
        }
    }
    __syncthreads();

    // phase 3: rescan with carry, write l2 + x splits
    s = car[k][ci];
#pragma unroll 4
    for (int i = 0; i < 64; i++) {
        float xv = xp[(size_t)(t0 + i) * Dd];
        s = 0.9f * s + 0.1f * xv;
        lp[(size_t)(t0 + i) * Dd] = s;
        __nv_bfloat16 h = __float2bfloat16(xv);
        xhp[(size_t)(t0 + i) * Dd] = h;
        xlp[(size_t)(t0 + i) * Dd] = __float2bfloat16(xv - __bfloat162float(h));
    }
}

// ================= HMMA bf16 hi/lo split GEMM =================
// C[M,N] = A[M,K]*B[N,K]^T, 3-pass hi/lo, fp32 accum. CTA 128x128, BK=32, 8 warps.
// EPI 0: plain fp32. 1: +bias,SiLU fp32. 3: bf16 split only. 5: permute fp32 + permuted split.
#define GBK 32
#define GSTR 80
#define GTILEB (128 * GSTR)
#define GSTAGE (4 * GTILEB)
#define GSMEM  (2 * GSTAGE)

template <int EPI>
__global__ void __launch_bounds__(256, 2)
gemm_tc(const __nv_bfloat16* __restrict__ Ah, const __nv_bfloat16* __restrict__ Al,
        const __nv_bfloat16* __restrict__ Bh, const __nv_bfloat16* __restrict__ Bl,
        const float* __restrict__ bias, float* __restrict__ C,
        __nv_bfloat16* __restrict__ Chi, __nv_bfloat16* __restrict__ Clo,
        int N, int K) {
    extern __shared__ char smem[];
    const uint32_t sbase = smem_to_u32(smem);
    const int tid = threadIdx.x;
    const int wid = tid >> 5, lane = tid & 31;
    const int wm = wid >> 2, wn = wid & 3;
    const int gid = lane >> 2, tig = lane & 3;
    const int m0 = blockIdx.y * 128, n0 = blockIdx.x * 128;

    const __nv_bfloat16* base[4] = {
        Ah + (size_t)m0 * K, Al + (size_t)m0 * K,
        Bh + (size_t)n0 * K, Bl + (size_t)n0 * K };

    float acc[4][4][4];
#pragma unroll
    for (int mi = 0; mi < 4; mi++)
#pragma unroll
        for (int nj = 0; nj < 4; nj++)
#pragma unroll
            for (int r = 0; r < 4; r++) acc[mi][nj][r] = 0.0f;

    const int NC = K / GBK;

#define LOAD_CHUNK(cc, ss) do { \
        int _c = (cc), _s = (ss); \
_Pragma("unroll") \
        for (int it = 0; it < 8; it++) { \
            int idx = tid + it * 256; \
            int tile = idx >> 9, row = (idx >> 2) & 127, ch = idx & 3; \
            const __nv_bfloat16* gp = base[tile] + (size_t)row * K + _c * GBK + ch * 8; \
            uint32_t sa = sbase + _s * GSTAGE + tile * GTILEB + row * GSTR + ch * 16; \
            CP_ASYNC16(sa, gp); \
        } \
    } while (0)

    LOAD_CHUNK(0, 0); CP_COMMIT();
    LOAD_CHUNK(1, 1); CP_COMMIT();

    const int lrow = lane & 15;
    const int lk8  = (lane >> 4) << 3;

    for (int c = 0; c < NC; c++) {
        const int s = c & 1;
        CP_WAIT1();
        __syncthreads();
        const uint32_t st = sbase + s * GSTAGE;
#pragma unroll
        for (int k16 = 0; k16 < 2; k16++) {
            const int k0 = k16 * 16;
            uint32_t bh[2][4], bl[2][4];
#pragma unroll
            for (int p = 0; p < 2; p++) {
                int n = wn * 32 + p * 16 + lrow;
                uint32_t ba = st + 2 * GTILEB + n * GSTR + (k0 + lk8) * 2;
                ldsm4(bh[p], ba);
                ldsm4(bl[p], ba + GTILEB);
            }
#pragma unroll
            for (int mi = 0; mi < 4; mi++) {
                int r = wm * 64 + mi * 16 + lrow;
                uint32_t aa = st + r * GSTR + (k0 + lk8) * 2;
                uint32_t ahf[4], alf[4];
                ldsm4(ahf, aa);
                ldsm4(alf, aa + GTILEB);
#pragma unroll
                for (int nj = 0; nj < 4; nj++) {
                    const int p = nj >> 1, q = nj & 1;
                    mma16816(acc[mi][nj], ahf, bh[p][q], bh[p][q + 2]);
                    mma16816(acc[mi][nj], ahf, bl[p][q], bl[p][q + 2]);
                    mma16816(acc[mi][nj], alf, bh[p][q], bh[p][q + 2]);
                }
            }
        }
        __syncthreads();
        if (c + 2 < NC) LOAD_CHUNK(c + 2, s);
        CP_COMMIT();
    }
#undef LOAD_CHUNK

    // -------- epilogue --------
#pragma unroll
    for (int mi = 0; mi < 4; mi++) {
#pragma unroll
        for (int nj = 0; nj < 4; nj++) {
            const int colw = wn * 32 + nj * 8 + tig * 2;
#pragma unroll
            for (int half = 0; half < 2; half++) {
                const int m = m0 + wm * 64 + mi * 16 + gid + half * 8;
                float v0 = acc[mi][nj][half * 2 + 0];
                float v1 = acc[mi][nj][half * 2 + 1];
                if (EPI == 1) {
                    v0 += bias[n0 + colw];
                    v1 += bias[n0 + colw + 1];
                    v0 = v0 / (1.0f + __expf(-v0));
                    v1 = v1 / (1.0f + __expf(-v1));
                }
                if (EPI == 5) {
                    const int bb = m >> 10, t = m & 1023, h = n0 >> 7;
                    size_t off = ((size_t)(bb * Hh + h) * Tt + t) * DH + colw;
                    *(float2*)(C + off) = make_float2(v0, v1);
                    split2(v0, v1, (__nv_bfloat162*)(Chi + off), (__nv_bfloat162*)(Clo + off));
                } else if (EPI == 3) {
                    size_t off = (size_t)m * N + n0 + colw;
                    split2(v0, v1, (__nv_bfloat162*)(Chi + off), (__nv_bfloat162*)(Clo + off));
                } else {
                    float* cp = C + (size_t)m * N + n0 + colw;
                    *(float2*)cp = make_float2(v0, v1);
                }
            }
        }
    }
}

// ---------------- router head ----------------
__global__ void router_kernel(const float* __restrict__ hdn, const float* __restrict__ rw2,
                              const float* __restrict__ rb2, float* __restrict__ lamA,
                              float* __restrict__ lamB) {
    int m = blockIdx.x;
    int tid = threadIdx.x;
    const float* hp = hdn + (size_t)m * DHALF;
    float p0 = 0.f, p1 = 0.f, p2 = 0.f;
    for (int k = tid; k < DHALF; k += 128) {
        float hv = hp[k];
        p0 = fmaf(hv, rw2[k], p0);
        p1 = fmaf(hv, rw2[DHALF + k], p1);
        p2 = fmaf(hv, rw2[2 * DHALF + k], p2);
    }
#pragma unroll
    for (int off = 16; off; off >>= 1) {
        p0 += __shfl_xor_sync(0xffffffffu, p0, off);
        p1 += __shfl_xor_sync(0xffffffffu, p1, off);
        p2 += __shfl_xor_sync(0xffffffffu, p2, off);
    }
    __shared__ float sbm[3][4];
    if ((tid & 31) == 0) {
        int w = tid >> 5;
        sbm[0][w] = p0; sbm[1][w] = p1; sbm[2][w] = p2;
    }
    __syncthreads();
    if (tid == 0) {
        float l0 = sbm[0][0] + sbm[0][1] + sbm[0][2] + sbm[0][3] + rb2[0];
        float l1 = sbm[1][0] + sbm[1][1] + sbm[1][2] + sbm[1][3] + rb2[1];
        float l2 = sbm[2][0] + sbm[2][1] + sbm[2][2] + sbm[2][3] + rb2[2];
        float mx = fmaxf(l0, fmaxf(l1, l2));
        float e0 = __expf(l0 - mx), e1 = __expf(l1 - mx), e2 = __expf(l2 - mx);
        float inv = 1.0f / (e0 + e1 + e2);
        float v0 = e0 * inv, v1 = e1 * inv, v2 = e2 * inv;
        lamA[m * 3 + 0] = v0; lamA[m * 3 + 1] = v1; lamA[m * 3 + 2] = v2;
        lamB[m * 3 + 0] = v0; lamB[m * 3 + 1] = v1; lamB[m * 3 + 2] = v2;
    }
}

// ---------------- fused = lam0*x + lam1*l2 + lam2*l3 -> bf16 hi/lo ----------------
__global__ void fuse_kernel(const float* __restrict__ x, const float* __restrict__ l2,
                            const float* __restrict__ l3, const float* __restrict__ lam,
                            __nv_bfloat16* __restrict__ fh, __nv_bfloat16* __restrict__ fl) {
    int idx = blockIdx.x * blockDim.x + threadIdx.x;
    if (idx >= Bb * Tt * Dd / 4) return;
    int m = idx / (Dd / 4);
    int c = (idx - m * (Dd / 4)) * 4;
    int b = m >> 10;
    const float* lp = lam + (size_t)m * 3;
    float a0 = lp[0], a1 = lp[1], a2 = lp[2];
    float4 xv = *(const float4*)(x + (size_t)m * Dd + c);
    float4 l2v = *(const float4*)(l2 + (size_t)m * Dd + c);
    float4 l3v = *(const float4*)(l3 + (size_t)b * Dd + c);
    float r0 = a0 * xv.x + a1 * l2v.x + a2 * l3v.x;
    float r1 = a0 * xv.y + a1 * l2v.y + a2 * l3v.y;
    float r2 = a0 * xv.z + a1 * l2v.z + a2 * l3v.z;
    float r3 = a0 * xv.w + a1 * l2v.w + a2 * l3v.w;
    size_t off = (size_t)m * Dd + c;
    split2(r0, r1, (__nv_bfloat162*)(fh + off),     (__nv_bfloat162*)(fl + off));
    split2(r2, r3, (__nv_bfloat162*)(fh + off) + 1, (__nv_bfloat162*)(fl + off) + 1);
}

// ================= HMMA flash attention (causal) =================
// CTA: 128 q-rows, 8 warps (16 rows each), j-blocks of 64, hi/lo 3-pass everywhere.
// smem: 2 K/V stages (Kh,Kl,Vh,Vl planes of 64x136 bf16) + P hi/lo (128x72 bf16).
#define KVSTR 136
#define KVPLANE (64 * KVSTR * 2)          // 17408
#define KVSTAGE (4 * KVPLANE)             // 69632
#define PSTR 72
#define PPLANE (128 * PSTR * 2)           // 18432
#define POFF (2 * KVSTAGE)                // 139264
#define ATTN_SMEM (2 * KVSTAGE + 2 * PPLANE)  // 176128

__global__ void __launch_bounds__(256, 1)
attn_tc(const __nv_bfloat16* __restrict__ qh, const __nv_bfloat16* __restrict__ ql,
        const __nv_bfloat16* __restrict__ khh, const __nv_bfloat16* __restrict__ khl,
        const __nv_bfloat16* __restrict__ vhh, const __nv_bfloat16* __restrict__ vhl,
        __nv_bfloat16* __restrict__ ah, __nv_bfloat16* __restrict__ al) {
    extern __shared__ char sm[];
    const uint32_t sbase = smem_to_u32(sm);
    const int tid = threadIdx.x;
    const int wid = tid >> 5, lane = tid & 31;
    const int gid = lane >> 2, tig = lane & 3;
    const int qb = 7 - blockIdx.x;            // heavy blocks first
    const int bh = blockIdx.y;
    const int b = bh >> 4, h = bh & 15;
    const int q0 = qb * 128;
    const float scale = 0.08838834764831845f;

    // ---- load Q hi/lo (128 x 128 bf16 each) into stage-0 area
    {
        const __nv_bfloat16* qhp = qh + (size_t)(b * Tt + q0) * Dd + h * DH;
        const __nv_bfloat16* qlp = ql + (size_t)(b * Tt + q0) * Dd + h * DH;
#pragma unroll
        for (int it = 0; it < 16; it++) {
            int idx = tid + it * 256;          // 0..4095
            int plane = idx >> 11;             // 0 = hi, 1 = lo
            int row = (idx >> 4) & 127, ch = idx & 15;
            const __nv_bfloat16* gp = (plane ? qlp : qhp) + (size_t)row * Dd + ch * 8;
            uint32_t sa = sbase + plane * (2 * KVPLANE) + row * (KVSTR * 2) + ch * 16;
            CP_ASYNC16(sa, gp);
        }
        CP_COMMIT(); CP_WAIT0();
        __syncthreads();
    }
    // ldmatrix Q fragments into registers (per warp: rows wid*16..+15)
    uint32_t qfh[8][4], qfl[8][4];
    {
        const int m0 = wid * 16;
#pragma unroll
        for (int k16 = 0; k16 < 8; k16++) {
            uint32_t addr = sbase + (m0 + (lane & 15)) * (KVSTR * 2)
                          + (k16 * 16 + ((lane >> 4) << 3)) * 2;
            ldsm4(qfh[k16], addr);
            ldsm4(qfl[k16], addr + 2 * KVPLANE);
        }
    }
    __syncthreads();   // Q smem area free for K/V stages

    float o[16][4];
#pragma unroll
    for (int nj = 0; nj < 16; nj++)
#pragma unroll
        for (int r = 0; r < 4; r++) o[nj][r] = 0.0f;
    float mi0 = -1e30f, mi1 = -1e30f, li0 = 0.0f, li1 = 0.0f;

    const __nv_bfloat16* kbh = khh + (size_t)(b * Hh + h) * Tt * DH;
    const __nv_bfloat16* kbl = khl + (size_t)(b * Hh + h) * Tt * DH;
    const __nv_bfloat16* vbh = vhh + (size_t)(b * Hh + h) * Tt * DH;
    const __nv_bfloat16* vbl = vhl + (size_t)(b * Hh + h) * Tt * DH;
    const int njb = 2 * qb + 2;

#define LOAD_KV(jjb, ss) do { \
        int _j0 = (jjb) * 64, _s = (ss); \
_Pragma("unroll") \
        for (int it = 0; it < 16; it++) { \
            int idx = tid + it * 256; \
            int plane = idx >> 10;                 /* 0 Kh,1 Kl,2 Vh,3 Vl */ \
            int row = (idx >> 4) & 63, ch = idx & 15; \
            const __nv_bfloat16* gp = \
                (plane == 0 ? kbh : plane == 1 ? kbl : plane == 2 ? vbh : vbl) \
                + (size_t)(_j0 + row) * DH + ch * 8; \
            uint32_t sa = sbase + _s * KVSTAGE + plane * KVPLANE + row * (KVSTR * 2) + ch * 16; \
            CP_ASYNC16(sa, gp); \
        } \
    } while (0)

    LOAD_KV(0, 0); CP_COMMIT();

    for (int jb = 0; jb < njb; jb++) {
        CP_WAIT0();
        __syncthreads();    // K/V stage ready; all warps past previous iter
        if (jb + 1 < njb) { LOAD_KV(jb + 1, (jb + 1) & 1); CP_COMMIT(); }
        const uint32_t st = sbase + (jb & 1) * KVSTAGE;

        // ---- S = Q K^T (3-pass hi/lo), warp computes m16 x n64
        float sacc[8][4];
#pragma unroll
        for (int nj = 0; nj < 8; nj++)
#pragma unroll
            for (int r = 0; r < 4; r++) sacc[nj][r] = 0.0f;

#pragma unroll
        for (int k16 = 0; k16 < 8; k16++) {
            const int k0 = k16 * 16;
#pragma unroll
            for (int p = 0; p < 4; p++) {
                uint32_t kfh[4], kfl[4];
                int n = p * 16 + (lane & 15);
                uint32_t ba = st + n * (KVSTR * 2) + (k0 + ((lane >> 4) << 3)) * 2;
                ldsm4(kfh, ba);
                ldsm4(kfl, ba + KVPLANE);
#pragma unroll
                for (int q = 0; q < 2; q++) {
                    int nj = p * 2 + q;
                    mma16816(sacc[nj], qfh[k16], kfh[q], kfh[q + 2]);
                    mma16816(sacc[nj], qfh[k16], kfl[q], kfl[q + 2]);
                    mma16816(sacc[nj], qfl[k16], kfh[q], kfh[q + 2]);
                }
            }
        }

        // scale + causal mask
#pragma unroll
        for (int nj = 0; nj < 8; nj++)
#pragma unroll
            for (int e = 0; e < 4; e++) sacc[nj][e] *= scale;
        if (jb >= 2 * qb) {
            const int rbase = q0 + wid * 16 + gid;
#pragma unroll
            for (int nj = 0; nj < 8; nj++)
#pragma unroll
                for (int e = 0; e < 4; e++) {
                    int col = jb * 64 + nj * 8 + tig * 2 + (e & 1);
                    int row = rbase + ((e >> 1) << 3);
                    if (col > row) sacc[nj][e] = -1e30f;
                }
        }

        // ---- online softmax (rows gid, gid+8; quad = 4 lanes share a row)
        float mx0 = -1e30f, mx1 = -1e30f;
#pragma unroll
        for (int nj = 0; nj < 8; nj++) {
            mx0 = fmaxf(mx0, fmaxf(sacc[nj][0], sacc[nj][1]));
            mx1 = fmaxf(mx1, fmaxf(sacc[nj][2], sacc[nj][3]));
        }
        mx0 = fmaxf(mx0, __shfl_xor_sync(0xffffffffu, mx0, 1));
        mx0 = fmaxf(mx0, __shfl_xor_sync(0xffffffffu, mx0, 2));
        mx1 = fmaxf(mx1, __shfl_xor_sync(0xffffffffu, mx1, 1));
        mx1 = fmaxf(mx1, __shfl_xor_sync(0xffffffffu, mx1, 2));
        float mn0 = fmaxf(mi0, mx0), mn1 = fmaxf(mi1, mx1);
        float corr0 = __expf(mi0 - mn0), corr1 = __expf(mi1 - mn1);
        float rs0 = 0.0f, rs1 = 0.0f;
#pragma unroll
        for (int nj = 0; nj < 8; nj++) {
            sacc[nj][0] = __expf(sacc[nj][0] - mn0); rs0 += sacc[nj][0];
            sacc[nj][1] = __expf(sacc[nj][1] - mn0); rs0 += sacc[nj][1];
            sacc[nj][2] = __expf(sacc[nj][2] - mn1); rs1 += sacc[nj][2];
            sacc[nj][3] = __expf(sacc[nj][3] - mn1); rs1 += sacc[nj][3];
        }
        rs0 += __shfl_xor_sync(0xffffffffu, rs0, 1);
        rs0 += __shfl_xor_sync(0xffffffffu, rs0, 2);
        rs1 += __shfl_xor_sync(0xffffffffu, rs1, 1);
        rs1 += __shfl_xor_sync(0xffffffffu, rs1, 2);
        li0 = li0 * corr0 + rs0; mi0 = mn0;
        li1 = li1 * corr1 + rs1; mi1 = mn1;
#pragma unroll
        for (int nj = 0; nj < 16; nj++) {
            o[nj][0] *= corr0; o[nj][1] *= corr0;
            o[nj][2] *= corr1; o[nj][3] *= corr1;
        }

        // ---- store P hi/lo to smem
        {
            const int pr0 = wid * 16 + gid;
#pragma unroll
            for (int nj = 0; nj < 8; nj++) {
                int col = nj * 8 + tig * 2;
                char* pp0 = sm + POFF + (pr0 * PSTR + col) * 2;
                char* pp1 = sm + POFF + ((pr0 + 8) * PSTR + col) * 2;
                split2(sacc[nj][0], sacc[nj][1], (__nv_bfloat162*)pp0,
                       (__nv_bfloat162*)(pp0 + PPLANE));
                split2(sacc[nj][2], sacc[nj][3], (__nv_bfloat162*)pp1,
                       (__nv_bfloat162*)(pp1 + PPLANE));
            }
        }
        __syncthreads();

        // ---- O += P V (3-pass hi/lo); V B-frags via ldmatrix.trans
#pragma unroll
        for (int k16 = 0; k16 < 4; k16++) {
            const int k0j = k16 * 16;
            uint32_t pfh[4], pfl[4];
            uint32_t aaddr = sbase + POFF
                + ((wid * 16 + (lane & 15)) * PSTR + k0j + ((lane >> 4) << 3)) * 2;
            ldsm4(pfh, aaddr);
            ldsm4(pfl, aaddr + PPLANE);
            const int mrow = k0j + (lane & 7) + ((lane >> 4) << 3);
            const int nc8 = ((lane >> 3) & 1) * 8;
#pragma unroll
            for (int p = 0; p < 8; p++) {
                uint32_t vfh[4], vfl[4];
                uint32_t vaddr = st + 2 * KVPLANE + mrow * (KVSTR * 2) + (p * 16 + nc8) * 2;
                ldsm4t(vfh, vaddr);
                ldsm4t(vfl, vaddr + KVPLANE);
#pragma unroll
                for (int q = 0; q < 2; q++) {
                    int nj = p * 2 + q;
                    mma16816(o[nj], pfh, vfh[q], vfh[q + 2]);
                    mma16816(o[nj], pfh, vfl[q], vfl[q + 2]);
                    mma16816(o[nj], pfl, vfh[q], vfh[q + 2]);
                }
            }
        }
    }
#undef LOAD_KV

    // ---- epilogue: normalize + bf16 hi/lo split to [b,t,d]
    const float inv0 = 1.0f / li0, inv1 = 1.0f / li1;
    const size_t row0 = (size_t)(b * Tt + q0 + wid * 16 + gid) * Dd + h * DH;
    const size_t row1 = row0 + 8 * Dd;
#pragma unroll
    for (int nj = 0; nj < 16; nj++) {
        int col = nj * 8 + tig * 2;
        split2(o[nj][0] * inv0, o[nj][1] * inv0,
               (__nv_bfloat162*)(ah + row0 + col), (__nv_bfloat162*)(al + row0 + col));
        split2(o[nj][2] * inv1, o[nj][3] * inv1,
               (__nv_bfloat162*)(ah + row1 + col), (__nv_bfloat162*)(al + row1 + col));
    }
}

// ---------------- launcher ----------------
extern "C" void kernel_launch(void* const* d_in, const int* in_sizes, int n_in,
                              void* d_out, int out_size) {
    (void)in_sizes; (void)n_in; (void)out_size;
    const float* x   = (const float*)d_in[0];
    const float* l3  = (const float*)d_in[1];
    const float* wq  = (const float*)d_in[2];
    const float* wk  = (const float*)d_in[3];
    const float* wv  = (const float*)d_in[4];
    const float* wo  = (const float*)d_in[5];
    const float* rw1 = (const float*)d_in[6];
    const float* rb1 = (const float*)d_in[7];
    const float* rw2 = (const float*)d_in[8];
    const float* rb2 = (const float*)d_in[9];

    float* out = (float*)d_out;
    float* kh  = out + (size_t)Bb * Tt * Dd;
    float* vh  = kh + (size_t)Bb * Tt * Dd;
    float* lam = vh + (size_t)Bb * Tt * Dd;

    float *pl2, *phdn, *plam;
    cudaGetSymbolAddress((void**)&pl2, g_l2);
    cudaGetSymbolAddress((void**)&phdn, g_hdn);
    cudaGetSymbolAddress((void**)&plam, g_lam);

    __nv_bfloat16 *xh,*xl,*wqh,*wql,*wkh,*wkl,*wvh,*wvl,*woh,*wol,*rw1h,*rw1l;
    __nv_bfloat16 *qh,*ql,*fh,*fl,*ah,*al,*khh,*khl,*vhh,*vhl;
    cudaGetSymbolAddress((void**)&xh, g_xh);   cudaGetSymbolAddress((void**)&xl, g_xl);
    cudaGetSymbolAddress((void**)&wqh, g_wqh); cudaGetSymbolAddress((void**)&wql, g_wql);
    cudaGetSymbolAddress((void**)&wkh, g_wkh); cudaGetSymbolAddress((void**)&wkl, g_wkl);
    cudaGetSymbolAddress((void**)&wvh, g_wvh); cudaGetSymbolAddress((void**)&wvl, g_wvl);
    cudaGetSymbolAddress((void**)&woh, g_woh); cudaGetSymbolAddress((void**)&wol, g_wol);
    cudaGetSymbolAddress((void**)&rw1h, g_rw1h); cudaGetSymbolAddress((void**)&rw1l, g_rw1l);
    cudaGetSymbolAddress((void**)&qh, g_qh);   cudaGetSymbolAddress((void**)&ql, g_ql);
    cudaGetSymbolAddress((void**)&fh, g_fh);   cudaGetSymbolAddress((void**)&fl, g_fl);
    cudaGetSymbolAddress((void**)&ah, g_ah);   cudaGetSymbolAddress((void**)&al, g_al);
    cudaGetSymbolAddress((void**)&khh, g_khh); cudaGetSymbolAddress((void**)&khl, g_khl);
    cudaGetSymbolAddress((void**)&vhh, g_vhh); cudaGetSymbolAddress((void**)&vhl, g_vhl);

    cudaFuncSetAttribute(attn_tc, cudaFuncAttributeMaxDynamicSharedMemorySize, ATTN_SMEM);
    cudaFuncSetAttribute(gemm_tc<0>, cudaFuncAttributeMaxDynamicSharedMemorySize, GSMEM);
    cudaFuncSetAttribute(gemm_tc<1>, cudaFuncAttributeMaxDynamicSharedMemorySize, GSMEM);
    cudaFuncSetAttribute(gemm_tc<3>, cudaFuncAttributeMaxDynamicSharedMemorySize, GSMEM);
    cudaFuncSetAttribute(gemm_tc<5>, cudaFuncAttributeMaxDynamicSharedMemorySize, GSMEM);

    const int NBIG4 = (MTOT * Dd) / 4;
    // 1. EMA scan (parallel chunked) + fused x split
    ema_kernel<<<256, 256>>>(x, pl2, xh, xl);
    // 2. weight splits (4 merged + rw1)
    SplitArgs sa;
    sa.s[0] = wq;  sa.h[0] = wqh; sa.l[0] = wql;
    sa.s[1] = wk;  sa.h[1] = wkh; sa.l[1] = wkl;
    sa.s[2] = wv;  sa.h[2] = wvh; sa.l[2] = wvl;
    sa.s[3] = wo;  sa.h[3] = woh; sa.l[3] = wol;
    split4_kernel<<<dim3((NBIG4 + 255) / 256, 4), 256>>>(sa, NBIG4);
    split_kernel<<<(NBIG4 / 2 + 255) / 256, 256>>>(rw1, rw1h, rw1l, NBIG4 / 2);
    // 3. q splits = x @ wq^T
    gemm_tc<3><<<dim3(16, 16), 256, GSMEM>>>(xh, xl, wqh, wql, nullptr, nullptr, qh, ql, Dd, Dd);
    // 4. hdn = silu(q @ rw1^T + rb1)
    gemm_tc<1><<<dim3(8, 16), 256, GSMEM>>>(qh, ql, rw1h, rw1l, rb1, phdn, nullptr, nullptr, DHALF, Dd);
    // 5. lam = softmax(hdn @ rw2^T + rb2)
    router_kernel<<<MTOT, 128>>>(phdn, rw2, rb2, plam, lam);
    // 6. fused mix -> bf16 splits
    fuse_kernel<<<(Bb * Tt * Dd / 4 + 255) / 256, 256>>>(x, pl2, l3, plam, fh, fl);
    // 7. kh/vh = heads(fused @ w^T): fp32 outputs + permuted bf16 splits for attention
    gemm_tc<5><<<dim3(16, 16), 256, GSMEM>>>(fh, fl, wkh, wkl, nullptr, kh, khh, khl, Dd, Dd);
    gemm_tc<5><<<dim3(16, 16), 256, GSMEM>>>(fh, fl, wvh, wvl, nullptr, vh, vhh, vhl, Dd, Dd);
    // 8. HMMA causal flash attention -> bf16 splits
    attn_tc<<<dim3(8, 32), 256, ATTN_SMEM>>>(qh, ql, khh, khl, vhh, vhl, ah, al);
    // 9. out = attn @ wo^T
    gemm_tc<0><<<dim3(16, 16), 256, GSMEM>>>(ah, al, woh, wol, nullptr, out, nullptr, nullptr, Dd, Dd);
}

// round 11
// speedup vs baseline: 5.1028x; 1.4047x over previous
#include <cuda_runtime.h>
#include <cuda_fp16.h>
#include <math.h>
#include <cstdint>

// Problem constants (fixed shapes)
#define Bb 2
#define Tt 1024
#define Dd 2048
#define Hh 16
#define DH 128
#define MTOT (Bb*Tt)      // 2048
#define DHALF (Dd/2)      // 1024

// ================= helpers (baseline PTX only — no 'a'-suffix features) =================
__device__ __forceinline__ uint32_t smem_to_u32(const void* p) {
    uint32_t a;
    asm("{ .reg .u64 t; cvta.to.shared.u64 t, %1; cvt.u32.u64 %0, t; }" : "=r"(a) : "l"(p));
    return a;
}
__device__ __forceinline__ void ldsm4(uint32_t* r, uint32_t addr) {
    asm volatile("ldmatrix.sync.aligned.m8n8.x4.shared.b16 {%0,%1,%2,%3}, [%4];"
        : "=r"(r[0]), "=r"(r[1]), "=r"(r[2]), "=r"(r[3]) : "r"(addr));
}
__device__ __forceinline__ void ldsm4t(uint32_t* r, uint32_t addr) {
    asm volatile("ldmatrix.sync.aligned.m8n8.x4.trans.shared.b16 {%0,%1,%2,%3}, [%4];"
        : "=r"(r[0]), "=r"(r[1]), "=r"(r[2]), "=r"(r[3]) : "r"(addr));
}
__device__ __forceinline__ void mma16816(float* c, const uint32_t* a, uint32_t b0, uint32_t b1) {
    asm volatile("mma.sync.aligned.m16n8k16.row.col.f32.f16.f16.f32 "
        "{%0,%1,%2,%3}, {%4,%5,%6,%7}, {%8,%9}, {%0,%1,%2,%3};"
        : "+f"(c[0]), "+f"(c[1]), "+f"(c[2]), "+f"(c[3])
        : "r"(a[0]), "r"(a[1]), "r"(a[2]), "r"(a[3]), "r"(b0), "r"(b1));
}
#define CP_ASYNC16(sa, gp) \
    asm volatile("cp.async.cg.shared.global [%0], [%1], 16;" :: "r"(sa), "l"(gp))
#define CP_COMMIT() asm volatile("cp.async.commit_group;" ::: "memory")
#define CP_WAIT1()  asm volatile("cp.async.wait_group 1;" ::: "memory")
#define CP_WAIT0()  asm volatile("cp.async.wait_group 0;" ::: "memory")

// ---------------- scratch (static device globals; no allocation) ----------------
__device__ float g_l2[MTOT*Dd];
__device__ float g_hdn[MTOT*DHALF];
__device__ float g_lam[MTOT*3];

// fp16 buffers: activations hi/lo, weights hi only
__device__ __half g_xh[MTOT*Dd],   g_xl[MTOT*Dd];
__device__ __half g_wqh[Dd*Dd];
__device__ __half g_wkh[Dd*Dd];
__device__ __half g_wvh[Dd*Dd];
__device__ __half g_woh[Dd*Dd];
__device__ __half g_rw1h[DHALF*Dd];
__device__ __half g_qh[MTOT*Dd],   g_ql[MTOT*Dd];
__device__ __half g_fh[MTOT*Dd],   g_fl[MTOT*Dd];
__device__ __half g_ah[MTOT*Dd],   g_al[MTOT*Dd];
__device__ __half g_khh[MTOT*Dd];   // [b,h,t,dh] fp16
__device__ __half g_vhh[MTOT*Dd];

// ---------------- fp32 -> fp16 hi/lo split helpers ----------------
__device__ __forceinline__ void split2h(float a, float b, __half2* hi, __half2* lo) {
    __half h0 = __float2half(a), h1 = __float2half(b);
    *hi = __halves2half2(h0, h1);
    *lo = __halves2half2(__float2half(a - __half2float(h0)),
                         __float2half(b - __half2float(h1)));
}

// 4 equally-sized weight fp32->fp16 conversions in one launch
struct CvtArgs { const float* s[4]; __half* h[4]; };
__global__ void cvt4_kernel(CvtArgs args, int n4) {
    int i = blockIdx.x * blockDim.x + threadIdx.x;
    if (i >= n4) return;
    int z = blockIdx.y;
    float4 v = ((const float4*)args.s[z])[i];
    ((__half2*)args.h[z])[2*i]   = __floats2half2_rn(v.x, v.y);
    ((__half2*)args.h[z])[2*i+1] = __floats2half2_rn(v.z, v.w);
}
__global__ void cvt_kernel(const float* __restrict__ s, __half* __restrict__ h, int n4) {
    int i = blockIdx.x * blockDim.x + threadIdx.x;
    if (i >= n4) return;
    float4 v = ((const float4*)s)[i];
    ((__half2*)h)[2*i]   = __floats2half2_rn(v.x, v.y);
    ((__half2*)h)[2*i+1] = __floats2half2_rn(v.z, v.w);
}

// ---------------- parallel chunked EMA scan + fused x hi/lo split ----------------
__global__ void __launch_bounds__(256)
ema_kernel(const float* __restrict__ x, float* __restrict__ l2,
           __half* __restrict__ xh, __half* __restrict__ xl) {
    const float P64 = 0.0011790184577738583f;   // 0.9^64
    int tid = threadIdx.x;
    int ci = tid & 15, k = tid >> 4;
    int b = blockIdx.x >> 7;
    int c = ((blockIdx.x & 127) << 4) + ci;
    const float* xp = x + (size_t)b * Tt * Dd + c;
    float* lp = l2 + (size_t)b * Tt * Dd + c;
    __half* xhp = xh + (size_t)b * Tt * Dd + c;
    __half* xlp = xl + (size_t)b * Tt * Dd + c;
    const int t0 = k * 64;

    float s = 0.0f;
#pragma unroll 4
    for (int i = 0; i < 64; i++)
        s = 0.9f * s + 0.1f * xp[(size_t)(t0 + i) * Dd];

    __shared__ float endv[16][17], car[16][17];
    endv[k][ci] = s;
    __syncthreads();
    if (k == 0) {
        float carry = 0.0f;
#pragma unroll
        for (int kk = 0; kk < 16; kk++) {
            car[kk][ci] = carry;
            carry = P64 * carry + endv[kk][ci];
        }
    }
    __syncthreads();

    s = car[k][ci];
#pragma unroll 4
    for (int i = 0; i < 64; i++) {
        float xv = xp[(size_t)(t0 + i) * Dd];
        s = 0.9f * s + 0.1f * xv;
        lp[(size_t)(t0 + i) * Dd] = s;
        __half h = __float2half(xv);
        xhp[(size_t)(t0 + i) * Dd] = h;
        xlp[(size_t)(t0 + i) * Dd] = __float2half(xv - __half2float(h));
    }
}

// ================= HMMA fp16 2-pass GEMM =================
// C[M,N] = A[M,K]*B[N,K]^T, D = (Ah+Al)*Bh, fp32 accum, err ~2^-12.
// CTA 128x128, BK=32, 8 warps, 3-stage cp.async pipeline, 1 barrier/chunk.
// EPI 0: plain fp32. 1: +bias,SiLU fp32. 3: fp16 hi/lo. 5: permute fp32 + permuted fp16 hi.
#define GBK 32
#define GSTR 80
#define GTILEB (128 * GSTR)           // 10240
#define GSTAGE (3 * GTILEB)           // 30720 (Ah, Al, Bh)
#define GSMEM  (3 * GSTAGE)           // 92160

template <int EPI>
__global__ void __launch_bounds__(256, 2)
gemm_tc(const __half* __restrict__ Ah, const __half* __restrict__ Al,
        const __half* __restrict__ Bh,
        const float* __restrict__ bias, float* __restrict__ C,
        __half* __restrict__ Chi, __half* __restrict__ Clo,
        int N, int K) {
    extern __shared__ char smem[];
    const uint32_t sbase = smem_to_u32(smem);
    const int tid = threadIdx.x;
    const int wid = tid >> 5, lane = tid & 31;
    const int wm = wid >> 2, wn = wid & 3;
    const int gid = lane >> 2, tig = lane & 3;
    const int m0 = blockIdx.y * 128, n0 = blockIdx.x * 128;

    const __half* base[3] = {
        Ah + (size_t)m0 * K, Al + (size_t)m0 * K, Bh + (size_t)n0 * K };

    float acc[4][4][4];
#pragma unroll
    for (int mi = 0; mi < 4; mi++)
#pragma unroll
        for (int nj = 0; nj < 4; nj++)
#pragma unroll
            for (int r = 0; r < 4; r++) acc[mi][nj][r] = 0.0f;

    const int NC = K / GBK;

#define LOAD_CHUNK(cc, ss) do { \
        int _c = (cc), _s = (ss); \
_Pragma("unroll") \
        for (int it = 0; it < 6; it++) { \
            int idx = tid + it * 256; \
            int tile = idx >> 9, row = (idx >> 2) & 127, ch = idx & 3; \
            const __half* gp = base[tile] + (size_t)row * K + _c * GBK + ch * 8; \
            uint32_t sa = sbase + _s * GSTAGE + tile * GTILEB + row * GSTR + ch * 16; \
            CP_ASYNC16(sa, gp); \
        } \
    } while (0)

    LOAD_CHUNK(0, 0); CP_COMMIT();
    LOAD_CHUNK(1, 1); CP_COMMIT();

    const int lrow = lane & 15;
    const int lk8  = (lane >> 4) << 3;
    int snext = 2;

    for (int c = 0; c < NC; c++) {
        CP_WAIT1();
        __syncthreads();
        if (c + 2 < NC) LOAD_CHUNK(c + 2, snext);
        CP_COMMIT();
        if (++snext == 3) snext = 0;
        const int s = c - (c / 3) * 3;
        const uint32_t st = sbase + s * GSTAGE;
#pragma unroll
        for (int k16 = 0; k16 < 2; k16++) {
            const int k0 = k16 * 16;
            uint32_t bh[2][4];
#pragma unroll
            for (int p = 0; p < 2; p++) {
                int n = wn * 32 + p * 16 + lrow;
                ldsm4(bh[p], st + 2 * GTILEB + n * GSTR + (k0 + lk8) * 2);
            }
#pragma unroll
            for (int mi = 0; mi < 4; mi++) {
                int r = wm * 64 + mi * 16 + lrow;
                uint32_t aa = st + r * GSTR + (k0 + lk8) * 2;
                uint32_t ahf[4], alf[4];
                ldsm4(ahf, aa);
                ldsm4(alf, aa + GTILEB);
#pragma unroll
                for (int nj = 0; nj < 4; nj++) {
                    const int p = nj >> 1, q = nj & 1;
                    mma16816(acc[mi][nj], ahf, bh[p][q], bh[p][q + 2]);
                    mma16816(acc[mi][nj], alf, bh[p][q], bh[p][q + 2]);
                }
            }
        }
    }
#undef LOAD_CHUNK

    // -------- epilogue --------
#pragma unroll
    for (int mi = 0; mi < 4; mi++) {
#pragma unroll
        for (int nj = 0; nj < 4; nj++) {
            const int colw = wn * 32 + nj * 8 + tig * 2;
#pragma unroll
            for (int half = 0; half < 2; half++) {
                const int m = m0 + wm * 64 + mi * 16 + gid + half * 8;
                float v0 = acc[mi][nj][half * 2 + 0];
                float v1 = acc[mi][nj][half * 2 + 1];
                if (EPI == 1) {
                    v0 += bias[n0 + colw];
                    v1 += bias[n0 + colw + 1];
                    v0 = v0 / (1.0f + __expf(-v0));
                    v1 = v1 / (1.0f + __expf(-v1));
                }
                if (EPI == 5) {
                    const int bb = m >> 10, t = m & 1023, h = n0 >> 7;
                    size_t off = ((size_t)(bb * Hh + h) * Tt + t) * DH + colw;
                    *(float2*)(C + off) = make_float2(v0, v1);
                    *(__half2*)(Chi + off) = __floats2half2_rn(v0, v1);
                } else if (EPI == 3) {
                    size_t off = (size_t)m * N + n0 + colw;
                    split2h(v0, v1, (__half2*)(Chi + off), (__half2*)(Clo + off));
                } else {
                    float* cp = C + (size_t)m * N + n0 + colw;
                    *(float2*)cp = make_float2(v0, v1);
                }
            }
        }
    }
}

// ---------------- router head ----------------
__global__ void router_kernel(const float* __restrict__ hdn, const float* __restrict__ rw2,
                              const float* __restrict__ rb2, float* __restrict__ lamA,
                              float* __restrict__ lamB) {
    int m = blockIdx.x;
    int tid = threadIdx.x;
    const float* hp = hdn + (size_t)m * DHALF;
    float p0 = 0.f, p1 = 0.f, p2 = 0.f;
    for (int k = tid; k < DHALF; k += 128) {
        float hv = hp[k];
        p0 = fmaf(hv, rw2[k], p0);
        p1 = fmaf(hv, rw2[DHALF + k], p1);
        p2 = fmaf(hv, rw2[2 * DHALF + k], p2);
    }
#pragma unroll
    for (int off = 16; off; off >>= 1) {
        p0 += __shfl_xor_sync(0xffffffffu, p0, off);
        p1 += __shfl_xor_sync(0xffffffffu, p1, off);
        p2 += __shfl_xor_sync(0xffffffffu, p2, off);
    }
    __shared__ float sbm[3][4];
    if ((tid & 31) == 0) {
        int w = tid >> 5;
        sbm[0][w] = p0; sbm[1][w] = p1; sbm[2][w] = p2;
    }
    __syncthreads();
    if (tid == 0) {
        float l0 = sbm[0][0] + sbm[0][1] + sbm[0][2] + sbm[0][3] + rb2[0];
        float l1 = sbm[1][0] + sbm[1][1] + sbm[1][2] + sbm[1][3] + rb2[1];
        float l2 = sbm[2][0] + sbm[2][1] + sbm[2][2] + sbm[2][3] + rb2[2];
        float mx = fmaxf(l0, fmaxf(l1, l2));
        float e0 = __expf(l0 - mx), e1 = __expf(l1 - mx), e2 = __expf(l2 - mx);
        float inv = 1.0f / (e0 + e1 + e2);
        float v0 = e0 * inv, v1 = e1 * inv, v2 = e2 * inv;
        lamA[m * 3 + 0] = v0; lamA[m * 3 + 1] = v1; lamA[m * 3 + 2] = v2;
        lamB[m * 3 + 0] = v0; lamB[m * 3 + 1] = v1; lamB[m * 3 + 2] = v2;
    }
}

// ---------------- fused = lam0*x + lam1*l2 + lam2*l3 -> fp16 hi/lo ----------------
__global__ void fuse_kernel(const float* __restrict__ x, const float* __restrict__ l2,
                            const float* __restrict__ l3, const float* __restrict__ lam,
                            __half* __restrict__ fh, __half* __restrict__ fl) {
    int idx = blockIdx.x * blockDim.x + threadIdx.x;
    if (idx >= Bb * Tt * Dd / 4) return;
    int m = idx / (Dd / 4);
    int c = (idx - m * (Dd / 4)) * 4;
    int b = m >> 10;
    const float* lp = lam + (size_t)m * 3;
    float a0 = lp[0], a1 = lp[1], a2 = lp[2];
    float4 xv = *(const float4*)(x + (size_t)m * Dd + c);
    float4 l2v = *(const float4*)(l2 + (size_t)m * Dd + c);
    float4 l3v = *(const float4*)(l3 + (size_t)b * Dd + c);
    float r0 = a0 * xv.x + a1 * l2v.x + a2 * l3v.x;
    float r1 = a0 * xv.y + a1 * l2v.y + a2 * l3v.y;
    float r2 = a0 * xv.z + a1 * l2v.z + a2 * l3v.z;
    float r3 = a0 * xv.w + a1 * l2v.w + a2 * l3v.w;
    size_t off = (size_t)m * Dd + c;
    split2h(r0, r1, (__half2*)(fh + off),     (__half2*)(fl + off));
    split2h(r2, r3, (__half2*)(fh + off) + 1, (__half2*)(fl + off) + 1);
}

// ================= HMMA flash attention (causal), fp16 2-pass =================
// CTA: 128 q-rows, 8 warps, j-blocks of 64. S=(Qh+Ql)Kh, O=(Ph+Pl)Vh.
// smem: 2 KV stages (Kh,Vh planes 64x136 fp16) + P hi/lo (128x72 fp16).
#define KVSTR 136
#define KVPLANE (64 * KVSTR * 2)          // 17408
#define KVSTAGE (2 * KVPLANE)             // 34816 (Kh, Vh)
#define PSTR 72
#define PPLANE (128 * PSTR * 2)           // 18432
#define POFF (2 * KVSTAGE)                // 69632
#define ATTN_SMEM (2 * KVSTAGE + 2 * PPLANE)  // 106496

__global__ void __launch_bounds__(256, 1)
attn_tc(const __half* __restrict__ qh, const __half* __restrict__ ql,
        const __half* __restrict__ khh, const __half* __restrict__ vhh,
        __half* __restrict__ ah, __half* __restrict__ al) {
    extern __shared__ char sm[];
    const uint32_t sbase = smem_to_u32(sm);
    const int tid = threadIdx.x;
    const int wid = tid >> 5, lane = tid & 31;
    const int gid = lane >> 2, tig = lane & 3;
    const int qb = 7 - blockIdx.x;            // heavy blocks first
    const int bh = blockIdx.y;
    const int b = bh >> 4, h = bh & 15;
    const int q0 = qb * 128;
    const float scale = 0.08838834764831845f;

    // ---- load Q hi/lo (128x128 fp16 each) into the 2 KV-stage areas
    {
        const __half* qhp = qh + (size_t)(b * Tt + q0) * Dd + h * DH;
        const __half* qlp = ql + (size_t)(b * Tt + q0) * Dd + h * DH;
#pragma unroll
        for (int it = 0; it < 16; it++) {
            int idx = tid + it * 256;
            int plane = idx >> 11;
            int row = (idx >> 4) & 127, ch = idx & 15;
            const __half* gp = (plane ? qlp : qhp) + (size_t)row * Dd + ch * 8;
            uint32_t sa = sbase + plane * KVSTAGE + row * (KVSTR * 2) + ch * 16;
            CP_ASYNC16(sa, gp);
        }
        CP_COMMIT(); CP_WAIT0();
        __syncthreads();
    }
    uint32_t qfh[8][4], qfl[8][4];
    {
        const int m0 = wid * 16;
#pragma unroll
        for (int k16 = 0; k16 < 8; k16++) {
            uint32_t addr = sbase + (m0 + (lane & 15)) * (KVSTR * 2)
                          + (k16 * 16 + ((lane >> 4) << 3)) * 2;
            ldsm4(qfh[k16], addr);
            ldsm4(qfl[k16], addr + KVSTAGE);
        }
    }
    __syncthreads();

    float o[16][4];
#pragma unroll
    for (int nj = 0; nj < 16; nj++)
#pragma unroll
        for (int r = 0; r < 4; r++) o[nj][r] = 0.0f;
    float mi0 = -1e30f, mi1 = -1e30f, li0 = 0.0f, li1 = 0.0f;

    const __half* kb = khh + (size_t)(b * Hh + h) * Tt * DH;
    const __half* vb = vhh + (size_t)(b * Hh + h) * Tt * DH;
    const int njb = 2 * qb + 2;

#define LOAD_KV(jjb, ss) do { \
        int _j0 = (jjb) * 64, _s = (ss); \
_Pragma("unroll") \
        for (int it = 0; it < 8; it++) { \
            int idx = tid + it * 256; \
            int plane = idx >> 10;                 /* 0 Kh, 1 Vh */ \
            int row = (idx >> 4) & 63, ch = idx & 15; \
            const __half* gp = (plane ? vb : kb) + (size_t)(_j0 + row) * DH + ch * 8; \
            uint32_t sa = sbase + _s * KVSTAGE + plane * KVPLANE + row * (KVSTR * 2) + ch * 16; \
            CP_ASYNC16(sa, gp); \
        } \
    } while (0)

    LOAD_KV(0, 0); CP_COMMIT();

    for (int jb = 0; jb < njb; jb++) {
        CP_WAIT0();
        __syncthreads();
        if (jb + 1 < njb) { LOAD_KV(jb + 1, (jb + 1) & 1); CP_COMMIT(); }
        const uint32_t st = sbase + (jb & 1) * KVSTAGE;

        // ---- S = (Qh+Ql) Kh, warp computes m16 x n64
        float sacc[8][4];
#pragma unroll
        for (int nj = 0; nj < 8; nj++)
#pragma unroll
            for (int r = 0; r < 4; r++) sacc[nj][r] = 0.0f;

#pragma unroll
        for (int k16 = 0; k16 < 8; k16++) {
            const int k0 = k16 * 16;
#pragma unroll
            for (int p = 0; p < 4; p++) {
                uint32_t kf[4];
                int n = p * 16 + (lane & 15);
                ldsm4(kf, st + n * (KVSTR * 2) + (k0 + ((lane >> 4) << 3)) * 2);
#pragma unroll
                for (int q = 0; q < 2; q++) {
                    int nj = p * 2 + q;
                    mma16816(sacc[nj], qfh[k16], kf[q], kf[q + 2]);
                    mma16816(sacc[nj], qfl[k16], kf[q], kf[q + 2]);
                }
            }
        }

        // scale + causal mask
#pragma unroll
        for (int nj = 0; nj < 8; nj++)
#pragma unroll
            for (int e = 0; e < 4; e++) sacc[nj][e] *= scale;
        if (jb >= 2 * qb) {
            const int rbase = q0 + wid * 16 + gid;
#pragma unroll
            for (int nj = 0; nj < 8; nj++)
#pragma unroll
                for (int e = 0; e < 4; e++) {
                    int col = jb * 64 + nj * 8 + tig * 2 + (e & 1);
                    int row = rbase + ((e >> 1) << 3);
                    if (col > row) sacc[nj][e] = -1e30f;
                }
        }

        // ---- online softmax
        float mx0 = -1e30f, mx1 = -1e30f;
#pragma unroll
        for (int nj = 0; nj < 8; nj++) {
            mx0 = fmaxf(mx0, fmaxf(sacc[nj][0], sacc[nj][1]));
            mx1 = fmaxf(mx1, fmaxf(sacc[nj][2], sacc[nj][3]));
        }
        mx0 = fmaxf(mx0, __shfl_xor_sync(0xffffffffu, mx0, 1));
        mx0 = fmaxf(mx0, __shfl_xor_sync(0xffffffffu, mx0, 2));
        mx1 = fmaxf(mx1, __shfl_xor_sync(0xffffffffu, mx1, 1));
        mx1 = fmaxf(mx1, __shfl_xor_sync(0xffffffffu, mx1, 2));
        float mn0 = fmaxf(mi0, mx0), mn1 = fmaxf(mi1, mx1);
        float corr0 = __expf(mi0 - mn0), corr1 = __expf(mi1 - mn1);
        float rs0 = 0.0f, rs1 = 0.0f;
#pragma unroll
        for (int nj = 0; nj < 8; nj++) {
            sacc[nj][0] = __expf(sacc[nj][0] - mn0); rs0 += sacc[nj][0];
            sacc[nj][1] = __expf(sacc[nj][1] - mn0); rs0 += sacc[nj][1];
            sacc[nj][2] = __expf(sacc[nj][2] - mn1); rs1 += sacc[nj][2];
            sacc[nj][3] = __expf(sacc[nj][3] - mn1); rs1 += sacc[nj][3];
        }
        rs0 += __shfl_xor_sync(0xffffffffu, rs0, 1);
        rs0 += __shfl_xor_sync(0xffffffffu, rs0, 2);
        rs1 += __shfl_xor_sync(0xffffffffu, rs1, 1);
        rs1 += __shfl_xor_sync(0xffffffffu, rs1, 2);
        li0 = li0 * corr0 + rs0; mi0 = mn0;
        li1 = li1 * corr1 + rs1; mi1 = mn1;
#pragma unroll
        for (int nj = 0; nj < 16; nj++) {
            o[nj][0] *= corr0; o[nj][1] *= corr0;
            o[nj][2] *= corr1; o[nj][3] *= corr1;
        }

        // ---- store P hi/lo to smem
        {
            const int pr0 = wid * 16 + gid;
#pragma unroll
            for (int nj = 0; nj < 8; nj++) {
                int col = nj * 8 + tig * 2;
                char* pp0 = sm + POFF + (pr0 * PSTR + col) * 2;
                char* pp1 = sm + POFF + ((pr0 + 8) * PSTR + col) * 2;
                split2h(sacc[nj][0], sacc[nj][1], (__half2*)pp0,
                        (__half2*)(pp0 + PPLANE));
                split2h(sacc[nj][2], sacc[nj][3], (__half2*)pp1,
                        (__half2*)(pp1 + PPLANE));
            }
        }
        __syncthreads();

        // ---- O += (Ph+Pl) Vh; V B-frags via ldmatrix.trans
#pragma unroll
        for (int k16 = 0; k16 < 4; k16++) {
            const int k0j = k16 * 16;
            uint32_t pfh[4], pfl[4];
            uint32_t aaddr = sbase + POFF
                + ((wid * 16 + (lane & 15)) * PSTR + k0j + ((lane >> 4) << 3)) * 2;
            ldsm4(pfh, aaddr);
            ldsm4(pfl, aaddr + PPLANE);
            const int mrow = k0j + (lane & 7) + ((lane >> 4) << 3);
            const int nc8 = ((lane >> 3) & 1) * 8;
#pragma unroll
            for (int p = 0; p < 8; p++) {
                uint32_t vf[4];
                ldsm4t(vf, st + KVPLANE + mrow * (KVSTR * 2) + (p * 16 + nc8) * 2);
#pragma unroll
                for (int q = 0; q < 2; q++) {
                    int nj = p * 2 + q;
                    mma16816(o[nj], pfh, vf[q], vf[q + 2]);
                    mma16816(o[nj], pfl, vf[q], vf[q + 2]);
                }
            }
        }
    }
#undef LOAD_KV

    // ---- epilogue: normalize + fp16 hi/lo split to [b,t,d]
    const float inv0 = 1.0f / li0, inv1 = 1.0f / li1;
    const size_t row0 = (size_t)(b * Tt + q0 + wid * 16 + gid) * Dd + h * DH;
    const size_t row1 = row0 + 8 * Dd;
#pragma unroll
    for (int nj = 0; nj < 16; nj++) {
        int col = nj * 8 + tig * 2;
        split2h(o[nj][0] * inv0, o[nj][1] * inv0,
                (__half2*)(ah + row0 + col), (__half2*)(al + row0 + col));
        split2h(o[nj][2] * inv1, o[nj][3] * inv1,
                (__half2*)(ah + row1 + col), (__half2*)(al + row1 + col));
    }
}

// ---------------- launcher ----------------
extern "C" void kernel_launch(void* const* d_in, const int* in_sizes, int n_in,
                              void* d_out, int out_size) {
    (void)in_sizes; (void)n_in; (void)out_size;
    const float* x   = (const float*)d_in[0];
    const float* l3  = (const float*)d_in[1];
    const float* wq  = (const float*)d_in[2];
    const float* wk  = (const float*)d_in[3];
    const float* wv  = (const float*)d_in[4];
    const float* wo  = (const float*)d_in[5];
    const float* rw1 = (const float*)d_in[6];
    const float* rb1 = (const float*)d_in[7];
    const float* rw2 = (const float*)d_in[8];
    const float* rb2 = (const float*)d_in[9];

    float* out = (float*)d_out;
    float* kh  = out + (size_t)Bb * Tt * Dd;
    float* vh  = kh + (size_t)Bb * Tt * Dd;
    float* lam = vh + (size_t)Bb * Tt * Dd;

    float *pl2, *phdn, *plam;
    cudaGetSymbolAddress((void**)&pl2, g_l2);
    cudaGetSymbolAddress((void**)&phdn, g_hdn);
    cudaGetSymbolAddress((void**)&plam, g_lam);

    __half *xh,*xl,*wqh,*wkh,*wvh,*woh,*rw1h;
    __half *qh,*ql,*fh,*fl,*ah,*al,*khh,*vhh;
    cudaGetSymbolAddress((void**)&xh, g_xh);   cudaGetSymbolAddress((void**)&xl, g_xl);
    cudaGetSymbolAddress((void**)&wqh, g_wqh);
    cudaGetSymbolAddress((void**)&wkh, g_wkh);
    cudaGetSymbolAddress((void**)&wvh, g_wvh);
    cudaGetSymbolAddress((void**)&woh, g_woh);
    cudaGetSymbolAddress((void**)&rw1h, g_rw1h);
    cudaGetSymbolAddress((void**)&qh, g_qh);   cudaGetSymbolAddress((void**)&ql, g_ql);
    cudaGetSymbolAddress((void**)&fh, g_fh);   cudaGetSymbolAddress((void**)&fl, g_fl);
    cudaGetSymbolAddress((void**)&ah, g_ah);   cudaGetSymbolAddress((void**)&al, g_al);
    cudaGetSymbolAddress((void**)&khh, g_khh);
    cudaGetSymbolAddress((void**)&vhh, g_vhh);

    cudaFuncSetAttribute(attn_tc, cudaFuncAttributeMaxDynamicSharedMemorySize, ATTN_SMEM);
    cudaFuncSetAttribute(gemm_tc<0>, cudaFuncAttributeMaxDynamicSharedMemorySize, GSMEM);
    cudaFuncSetAttribute(gemm_tc<1>, cudaFuncAttributeMaxDynamicSharedMemorySize, GSMEM);
    cudaFuncSetAttribute(gemm_tc<3>, cudaFuncAttributeMaxDynamicSharedMemorySize, GSMEM);
    cudaFuncSetAttribute(gemm_tc<5>, cudaFuncAttributeMaxDynamicSharedMemorySize, GSMEM);

    const int NBIG4 = (MTOT * Dd) / 4;
    // 1. EMA scan + fused x hi/lo split
    ema_kernel<<<256, 256>>>(x, pl2, xh, xl);
    // 2. weight fp16 conversions (4 merged + rw1)
    CvtArgs ca;
    ca.s[0] = wq;  ca.h[0] = wqh;
    ca.s[1] = wk;  ca.h[1] = wkh;
    ca.s[2] = wv;  ca.h[2] = wvh;
    ca.s[3] = wo;  ca.h[3] = woh;
    cvt4_kernel<<<dim3((NBIG4 + 255) / 256, 4), 256>>>(ca, NBIG4);
    cvt_kernel<<<(NBIG4 / 2 + 255) / 256, 256>>>(rw1, rw1h, NBIG4 / 2);
    // 3. q hi/lo = x @ wq^T
    gemm_tc<3><<<dim3(16, 16), 256, GSMEM>>>(xh, xl, wqh, nullptr, nullptr, qh, ql, Dd, Dd);
    // 4. hdn = silu(q @ rw1^T + rb1)
    gemm_tc<1><<<dim3(8, 16), 256, GSMEM>>>(qh, ql, rw1h, rb1, phdn, nullptr, nullptr, DHALF, Dd);
    // 5. lam = softmax(hdn @ rw2^T + rb2)
    router_kernel<<<MTOT, 128>>>(phdn, rw2, rb2, plam, lam);
    // 6. fused mix -> fp16 hi/lo
    fuse_kernel<<<(Bb * Tt * Dd / 4 + 255) / 256, 256>>>(x, pl2, l3, plam, fh, fl);
    // 7. kh/vh = heads(fused @ w^T): fp32 outputs + permuted fp16 for attention
    gemm_tc<5><<<dim3(16, 16), 256, GSMEM>>>(fh, fl, wkh, nullptr, kh, khh, nullptr, Dd, Dd);
    gemm_tc<5><<<dim3(16, 16), 256, GSMEM>>>(fh, fl, wvh, nullptr, vh, vhh, nullptr, Dd, Dd);
    // 8. HMMA causal flash attention -> fp16 hi/lo
    attn_tc<<<dim3(8, 32), 256, ATTN_SMEM>>>(qh, ql, khh, vhh, ah, al);
    // 9. out = attn @ wo^T
    gemm_tc<0><<<dim3(16, 16), 256, GSMEM>>>(ah, al, woh, nullptr, out, nullptr, nullptr, Dd, Dd);
}

// round 14
// speedup vs baseline: 5.4059x; 1.0594x over previous
#include <cuda_runtime.h>
#include <cuda_fp16.h>
#include <math.h>
#include <cstdint>

// Problem constants (fixed shapes)
#define Bb 2
#define Tt 1024
#define Dd 2048
#define Hh 16
#define DH 128
#define MTOT (Bb*Tt)      // 2048
#define DHALF (Dd/2)      // 1024

// ================= helpers (baseline PTX only — no 'a'-suffix features) =================
__device__ __forceinline__ uint32_t smem_to_u32(const void* p) {
    uint32_t a;
    asm("{ .reg .u64 t; cvta.to.shared.u64 t, %1; cvt.u32.u64 %0, t; }" : "=r"(a) : "l"(p));
    return a;
}
__device__ __forceinline__ void ldsm4(uint32_t* r, uint32_t addr) {
    asm volatile("ldmatrix.sync.aligned.m8n8.x4.shared.b16 {%0,%1,%2,%3}, [%4];"
        : "=r"(r[0]), "=r"(r[1]), "=r"(r[2]), "=r"(r[3]) : "r"(addr));
}
__device__ __forceinline__ void ldsm4t(uint32_t* r, uint32_t addr) {
    asm volatile("ldmatrix.sync.aligned.m8n8.x4.trans.shared.b16 {%0,%1,%2,%3}, [%4];"
        : "=r"(r[0]), "=r"(r[1]), "=r"(r[2]), "=r"(r[3]) : "r"(addr));
}
__device__ __forceinline__ void mma16816(float* c, const uint32_t* a, uint32_t b0, uint32_t b1) {
    asm volatile("mma.sync.aligned.m16n8k16.row.col.f32.f16.f16.f32 "
        "{%0,%1,%2,%3}, {%4,%5,%6,%7}, {%8,%9}, {%0,%1,%2,%3};"
        : "+f"(c[0]), "+f"(c[1]), "+f"(c[2]), "+f"(c[3])
        : "r"(a[0]), "r"(a[1]), "r"(a[2]), "r"(a[3]), "r"(b0), "r"(b1));
}
#define CP_ASYNC16(sa, gp) \
    asm volatile("cp.async.cg.shared.global [%0], [%1], 16;" :: "r"(sa), "l"(gp))
#define CP_COMMIT() asm volatile("cp.async.commit_group;" ::: "memory")
#define CP_WAIT1()  asm volatile("cp.async.wait_group 1;" ::: "memory")
#define CP_WAIT0()  asm volatile("cp.async.wait_group 0;" ::: "memory")

// ---------------- scratch (static device globals; no allocation) ----------------
__device__ float g_l2[MTOT*Dd];
__device__ float g_hdn[MTOT*DHALF];
__device__ float g_lam[MTOT*3];

// fp16 buffers: activations hi/lo, weights hi only
__device__ __half g_xh[MTOT*Dd],   g_xl[MTOT*Dd];
__device__ __half g_wqh[Dd*Dd];
__device__ __half g_wkh[Dd*Dd];
__device__ __half g_wvh[Dd*Dd];
__device__ __half g_woh[Dd*Dd];
__device__ __half g_rw1h[DHALF*Dd];
__device__ __half g_qh[MTOT*Dd],   g_ql[MTOT*Dd];
__device__ __half g_fh[MTOT*Dd],   g_fl[MTOT*Dd];
__device__ __half g_ah[MTOT*Dd],   g_al[MTOT*Dd];
__device__ __half g_khh[MTOT*Dd];   // [b,h,t,dh] fp16
__device__ __half g_vhh[MTOT*Dd];

// ---------------- fp32 -> fp16 hi/lo split helpers ----------------
__device__ __forceinline__ void split2h(float a, float b, __half2* hi, __half2* lo) {
    __half h0 = __float2half(a), h1 = __float2half(b);
    *hi = __halves2half2(h0, h1);
    *lo = __halves2half2(__float2half(a - __half2float(h0)),
                         __float2half(b - __half2float(h1)));
}

// 4 equally-sized weight fp32->fp16 conversions in one launch
struct CvtArgs { const float* s[4]; __half* h[4]; };
__global__ void cvt4_kernel(CvtArgs args, int n4) {
    int i = blockIdx.x * blockDim.x + threadIdx.x;
    if (i >= n4) return;
    int z = blockIdx.y;
    float4 v = ((const float4*)args.s[z])[i];
    ((__half2*)args.h[z])[2*i]   = __floats2half2_rn(v.x, v.y);
    ((__half2*)args.h[z])[2*i+1] = __floats2half2_rn(v.z, v.w);
}
__global__ void cvt_kernel(const float* __restrict__ s, __half* __restrict__ h, int n4) {
    int i = blockIdx.x * blockDim.x + threadIdx.x;
    if (i >= n4) return;
    float4 v = ((const float4*)s)[i];
    ((__half2*)h)[2*i]   = __floats2half2_rn(v.x, v.y);
    ((__half2*)h)[2*i+1] = __floats2half2_rn(v.z, v.w);
}

// ---------------- parallel chunked EMA scan + fused x hi/lo split ----------------
__global__ void __launch_bounds__(256)
ema_kernel(const float* __restrict__ x, float* __restrict__ l2,
           __half* __restrict__ xh, __half* __restrict__ xl) {
    const float P64 = 0.0011790184577738583f;   // 0.9^64
    int tid = threadIdx.x;
    int ci = tid & 15, k = tid >> 4;
    int b = blockIdx.x >> 7;
    int c = ((blockIdx.x & 127) << 4) + ci;
    const float* xp = x + (size_t)b * Tt * Dd + c;
    float* lp = l2 + (size_t)b * Tt * Dd + c;
    __half* xhp = xh + (size_t)b * Tt * Dd + c;
    __half* xlp = xl + (size_t)b * Tt * Dd + c;
    const int t0 = k * 64;

    float s = 0.0f;
#pragma unroll 4
    for (int i = 0; i < 64; i++)
        s = 0.9f * s + 0.1f * xp[(size_t)(t0 + i) * Dd];

    __shared__ float endv[16][17], car[16][17];
    endv[k][ci] = s;
    __syncthreads();
    if (k == 0) {
        float carry = 0.0f;
#pragma unroll
        for (int kk = 0; kk < 16; kk++) {
            car[kk][ci] = carry;
            carry = P64 * carry + endv[kk][ci];
        }
    }
    __syncthreads();

    s = car[k][ci];
#pragma unroll 4
    for (int i = 0; i < 64; i++) {
        float xv = xp[(size_t)(t0 + i) * Dd];
        s = 0.9f * s + 0.1f * xv;
        lp[(size_t)(t0 + i) * Dd] = s;
        __half h = __float2half(xv);
        xhp[(size_t)(t0 + i) * Dd] = h;
        xlp[(size_t)(t0 + i) * Dd] = __float2half(xv - __half2float(h));
    }
}

// ================= HMMA fp16 2-pass GEMM =================
// C[M,N] = A[M,K]*B[N,K]^T, D = (Ah+Al)*Bh, fp32 accum.
// CTA 128x128, BK=64, warp grid 4(m)x2(n), warp tile 32x64 (4.0 MMA/ldsm),
// 2-stage cp.async pipeline. EPI 0: plain fp32. 1: +bias,SiLU. 3: fp16 hi/lo.
// 5: permute fp32 + permuted fp16 hi, dual-weight via blockIdx.z.
#define GBK 64
#define GSTR 144                      // 128B row + 16B pad: 8-row ldsm phase conflict-free
#define GTILEB (128 * GSTR)           // 18432
#define GSTAGE (3 * GTILEB)           // 55296 (Ah, Al, Bh)
#define GSMEM  (2 * GSTAGE)           // 110592

template <int EPI>
__global__ void __launch_bounds__(256, 2)
gemm_tc(const __half* __restrict__ Ah, const __half* __restrict__ Al,
        const __half* __restrict__ Bh, const __half* __restrict__ Bh2,
        const float* __restrict__ bias, float* __restrict__ C, float* __restrict__ C2,
        __half* __restrict__ Chi, __half* __restrict__ Chi2, __half* __restrict__ Clo,
        int N, int K) {
    extern __shared__ char smem[];
    const uint32_t sbase = smem_to_u32(smem);
    const int tid = threadIdx.x;
    const int wid = tid >> 5, lane = tid & 31;
    const int wm = wid & 3, wn = wid >> 2;       // 4(m) x 2(n)
    const int gid = lane >> 2, tig = lane & 3;
    const int m0 = blockIdx.y * 128, n0 = blockIdx.x * 128;

    const __half* Bsel = (EPI == 5 && blockIdx.z) ? Bh2 : Bh;
    float* Csel = (EPI == 5 && blockIdx.z) ? C2 : C;
    __half* Chisel = (EPI == 5 && blockIdx.z) ? Chi2 : Chi;

    const __half* base[3] = {
        Ah + (size_t)m0 * K, Al + (size_t)m0 * K, Bsel + (size_t)n0 * K };

    float acc[2][8][4];
#pragma unroll
    for (int mi = 0; mi < 2; mi++)
#pragma unroll
        for (int nj = 0; nj < 8; nj++)
#pragma unroll
            for (int r = 0; r < 4; r++) acc[mi][nj][r] = 0.0f;

    const int NC = K / GBK;

#define LOAD_CHUNK(cc, ss) do { \
        int _c = (cc), _s = (ss); \
_Pragma("unroll") \
        for (int it = 0; it < 12; it++) { \
            int idx = tid + it * 256; \
            int tile = idx >> 10, row = (idx >> 3) & 127, ch = idx & 7; \
            const __half* gp = base[tile] + (size_t)row * K + _c * GBK + ch * 8; \
            uint32_t sa = sbase + _s * GSTAGE + tile * GTILEB + row * GSTR + ch * 16; \
            CP_ASYNC16(sa, gp); \
        } \
    } while (0)

    LOAD_CHUNK(0, 0); CP_COMMIT();

    const int lrow = lane & 15;
    const int lk8  = (lane >> 4) << 3;

    for (int c = 0; c < NC; c++) {
        if (c + 1 < NC) { LOAD_CHUNK(c + 1, (c + 1) & 1); CP_COMMIT(); CP_WAIT1(); }
        else            { CP_WAIT0(); }
        __syncthreads();
        const uint32_t st = sbase + (c & 1) * GSTAGE;
#pragma unroll
        for (int k16 = 0; k16 < 4; k16++) {
            const int k0 = k16 * 16;
            uint32_t bf[4][4];
#pragma unroll
            for (int p = 0; p < 4; p++) {
                int n = wn * 64 + p * 16 + lrow;
                ldsm4(bf[p], st + 2 * GTILEB + n * GSTR + (k0 + lk8) * 2);
            }
#pragma unroll
            for (int mi = 0; mi < 2; mi++) {
                int r = wm * 32 + mi * 16 + lrow;
                uint32_t aa = st + r * GSTR + (k0 + lk8) * 2;
                uint32_t ahf[4], alf[4];
                ldsm4(ahf, aa);
                ldsm4(alf, aa + GTILEB);
#pragma unroll
                for (int nj = 0; nj < 8; nj++) {
                    const int p = nj >> 1, q = nj & 1;
                    mma16816(acc[mi][nj], ahf, bf[p][q], bf[p][q + 2]);
                    mma16816(acc[mi][nj], alf, bf[p][q], bf[p][q + 2]);
                }
            }
        }
        __syncthreads();   // stage (c) free before LOAD of (c+2) next iter
    }
#undef LOAD_CHUNK

    // -------- epilogue --------
#pragma unroll
    for (int mi = 0; mi < 2; mi++) {
#pragma unroll
        for (int nj = 0; nj < 8; nj++) {
            const int colw = wn * 64 + nj * 8 + tig * 2;
#pragma unroll
            for (int half = 0; half < 2; half++) {
                const int m = m0 + wm * 32 + mi * 16 + gid + half * 8;
                float v0 = acc[mi][nj][half * 2 + 0];
                float v1 = acc[mi][nj][half * 2 + 1];
                if (EPI == 1) {
                    v0 += bias[n0 + colw];
                    v1 += bias[n0 + colw + 1];
                    v0 = v0 / (1.0f + __expf(-v0));
                    v1 = v1 / (1.0f + __expf(-v1));
                }
                if (EPI == 5) {
                    const int bb = m >> 10, t = m & 1023, h = n0 >> 7;
                    size_t off = ((size_t)(bb * Hh + h) * Tt + t) * DH + colw;
                    *(float2*)(Csel + off) = make_float2(v0, v1);
                    *(__half2*)(Chisel + off) = __floats2half2_rn(v0, v1);
                } else if (EPI == 3) {
                    size_t off = (size_t)m * N + n0 + colw;
                    split2h(v0, v1, (__half2*)(Chi + off), (__half2*)(Clo + off));
                } else {
                    float* cp = Csel + (size_t)m * N + n0 + colw;
                    *(float2*)cp = make_float2(v0, v1);
                }
            }
        }
    }
}

// ---------------- router head ----------------
__global__ void router_kernel(const float* __restrict__ hdn, const float* __restrict__ rw2,
                              const float* __restrict__ rb2, float* __restrict__ lamA,
                              float* __restrict__ lamB) {
    int m = blockIdx.x;
    int tid = threadIdx.x;
    const float* hp = hdn + (size_t)m * DHALF;
    float p0 = 0.f, p1 = 0.f, p2 = 0.f;
    for (int k = tid; k < DHALF; k += 128) {
        float hv = hp[k];
        p0 = fmaf(hv, rw2[k], p0);
        p1 = fmaf(hv, rw2[DHALF + k], p1);
        p2 = fmaf(hv, rw2[2 * DHALF + k], p2);
    }
#pragma unroll
    for (int off = 16; off; off >>= 1) {
        p0 += __shfl_xor_sync(0xffffffffu, p0, off);
        p1 += __shfl_xor_sync(0xffffffffu, p1, off);
        p2 += __shfl_xor_sync(0xffffffffu, p2, off);
    }
    __shared__ float sbm[3][4];
    if ((tid & 31) == 0) {
        int w = tid >> 5;
        sbm[0][w] = p0; sbm[1][w] = p1; sbm[2][w] = p2;
    }
    __syncthreads();
    if (tid == 0) {
        float l0 = sbm[0][0] + sbm[0][1] + sbm[0][2] + sbm[0][3] + rb2[0];
        float l1 = sbm[1][0] + sbm[1][1] + sbm[1][2] + sbm[1][3] + rb2[1];
        float l2 = sbm[2][0] + sbm[2][1] + sbm[2][2] + sbm[2][3] + rb2[2];
        float mx = fmaxf(l0, fmaxf(l1, l2));
        float e0 = __expf(l0 - mx), e1 = __expf(l1 - mx), e2 = __expf(l2 - mx);
        float inv = 1.0f / (e0 + e1 + e2);
        float v0 = e0 * inv, v1 = e1 * inv, v2 = e2 * inv;
        lamA[m * 3 + 0] = v0; lamA[m * 3 + 1] = v1; lamA[m * 3 + 2] = v2;
        lamB[m * 3 + 0] = v0; lamB[m * 3 + 1] = v1; lamB[m * 3 + 2] = v2;
    }
}

// ---------------- fused = lam0*x + lam1*l2 + lam2*l3 -> fp16 hi/lo ----------------
__global__ void fuse_kernel(const float* __restrict__ x, const float* __restrict__ l2,
                            const float* __restrict__ l3, const float* __restrict__ lam,
                            __half* __restrict__ fh, __half* __restrict__ fl) {
    int idx = blockIdx.x * blockDim.x + threadIdx.x;
    if (idx >= Bb * Tt * Dd / 4) return;
    int m = idx / (Dd / 4);
    int c = (idx - m * (Dd / 4)) * 4;
    int b = m >> 10;
    const float* lp = lam + (size_t)m * 3;
    float a0 = lp[0], a1 = lp[1], a2 = lp[2];
    float4 xv = *(const float4*)(x + (size_t)m * Dd + c);
    float4 l2v = *(const float4*)(l2 + (size_t)m * Dd + c);
    float4 l3v = *(const float4*)(l3 + (size_t)b * Dd + c);
    float r0 = a0 * xv.x + a1 * l2v.x + a2 * l3v.x;
    float r1 = a0 * xv.y + a1 * l2v.y + a2 * l3v.y;
    float r2 = a0 * xv.z + a1 * l2v.z + a2 * l3v.z;
    float r3 = a0 * xv.w + a1 * l2v.w + a2 * l3v.w;
    size_t off = (size_t)m * Dd + c;
    split2h(r0, r1, (__half2*)(fh + off),     (__half2*)(fl + off));
    split2h(r2, r3, (__half2*)(fh + off) + 1, (__half2*)(fl + off) + 1);
}

// ================= HMMA flash attention (causal), fp16 2-pass =================
// CTA: 128 q-rows, 8 warps, j-blocks of 64. S=(Qh+Ql)Kh, O=(Ph+Pl)Vh.
#define KVSTR 136
#define KVPLANE (64 * KVSTR * 2)          // 17408
#define KVSTAGE (2 * KVPLANE)             // 34816 (Kh, Vh)
#define PSTR 72
#define PPLANE (128 * PSTR * 2)           // 18432
#define POFF (2 * KVSTAGE)                // 69632
#define ATTN_SMEM (2 * KVSTAGE + 2 * PPLANE)  // 106496

__global__ void __launch_bounds__(256, 1)
attn_tc(const __half* __restrict__ qh, const __half* __restrict__ ql,
        const __half* __restrict__ khh, const __half* __restrict__ vhh,
        __half* __restrict__ ah, __half* __restrict__ al) {
    extern __shared__ char sm[];
    const uint32_t sbase = smem_to_u32(sm);
    const int tid = threadIdx.x;
    const int wid = tid >> 5, lane = tid & 31;
    const int gid = lane >> 2, tig = lane & 3;
    const int qb = 7 - blockIdx.x;            // heavy blocks first
    const int bh = blockIdx.y;
    const int b = bh >> 4, h = bh & 15;
    const int q0 = qb * 128;
    const float scale = 0.08838834764831845f;

    // ---- load Q hi/lo (128x128 fp16 each) into the 2 KV-stage areas
    {
        const __half* qhp = qh + (size_t)(b * Tt + q0) * Dd + h * DH;
        const __half* qlp = ql + (size_t)(b * Tt + q0) * Dd + h * DH;
#pragma unroll
        for (int it = 0; it < 16; it++) {
            int idx = tid + it * 256;
            int plane = idx >> 11;
            int row = (idx >> 4) & 127, ch = idx & 15;
            const __half* gp = (plane ? qlp : qhp) + (size_t)row * Dd + ch * 8;
            uint32_t sa = sbase + plane * KVSTAGE + row * (KVSTR * 2) + ch * 16;
            CP_ASYNC16(sa, gp);
        }
        CP_COMMIT(); CP_WAIT0();
        __syncthreads();
    }
    uint32_t qfh[8][4], qfl[8][4];
    {
        const int m0 = wid * 16;
#pragma unroll
        for (int k16 = 0; k16 < 8; k16++) {
            uint32_t addr = sbase + (m0 + (lane & 15)) * (KVSTR * 2)
                          + (k16 * 16 + ((lane >> 4) << 3)) * 2;
            ldsm4(qfh[k16], addr);
            ldsm4(qfl[k16], addr + KVSTAGE);
        }
    }
    __syncthreads();

    float o[16][4];
#pragma unroll
    for (int nj = 0; nj < 16; nj++)
#pragma unroll
        for (int r = 0; r < 4; r++) o[nj][r] = 0.0f;
    float mi0 = -1e30f, mi1 = -1e30f, li0 = 0.0f, li1 = 0.0f;

    const __half* kb = khh + (size_t)(b * Hh + h) * Tt * DH;
    const __half* vb = vhh + (size_t)(b * Hh + h) * Tt * DH;
    const int njb = 2 * qb + 2;

#define LOAD_KV(jjb, ss) do { \
        int _j0 = (jjb) * 64, _s = (ss); \
_Pragma("unroll") \
        for (int it = 0; it < 8; it++) { \
            int idx = tid + it * 256; \
            int plane = idx >> 10; \
            int row = (idx >> 4) & 63, ch = idx & 15; \
            const __half* gp = (plane ? vb : kb) + (size_t)(_j0 + row) * DH + ch * 8; \
            uint32_t sa = sbase + _s * KVSTAGE + plane * KVPLANE + row * (KVSTR * 2) + ch * 16; \
            CP_ASYNC16(sa, gp); \
        } \
    } while (0)

    LOAD_KV(0, 0); CP_COMMIT();

    for (int jb = 0; jb < njb; jb++) {
        CP_WAIT0();
        __syncthreads();
        if (jb + 1 < njb) { LOAD_KV(jb + 1, (jb + 1) & 1); CP_COMMIT(); }
        const uint32_t st = sbase + (jb & 1) * KVSTAGE;

        // ---- S = (Qh+Ql) Kh, warp computes m16 x n64
        float sacc[8][4];
#pragma unroll
        for (int nj = 0; nj < 8; nj++)
#pragma unroll
            for (int r = 0; r < 4; r++) sacc[nj][r] = 0.0f;

#pragma unroll
        for (int k16 = 0; k16 < 8; k16++) {
            const int k0 = k16 * 16;
#pragma unroll
            for (int p = 0; p < 4; p++) {
                uint32_t kf[4];
                int n = p * 16 + (lane & 15);
                ldsm4(kf, st + n * (KVSTR * 2) + (k0 + ((lane >> 4) << 3)) * 2);
#pragma unroll
                for (int q = 0; q < 2; q++) {
                    int nj = p * 2 + q;
                    mma16816(sacc[nj], qfh[k16], kf[q], kf[q + 2]);
                    mma16816(sacc[nj], qfl[k16], kf[q], kf[q + 2]);
                }
            }
        }

        // scale + causal mask
#pragma unroll
        for (int nj = 0; nj < 8; nj++)
#pragma unroll
            for (int e = 0; e < 4; e++) sacc[nj][e] *= scale;
        if (jb >= 2 * qb) {
            const int rbase = q0 + wid * 16 + gid;
#pragma unroll
            for (int nj = 0; nj < 8; nj++)
#pragma unroll
                for (int e = 0; e < 4; e++) {
                    int col = jb * 64 + nj * 8 + tig * 2 + (e & 1);
                    int row = rbase + ((e >> 1) << 3);
                    if (col > row) sacc[nj][e] = -1e30f;
                }
        }

        // ---- online softmax
        float mx0 = -1e30f, mx1 = -1e30f;
#pragma unroll
        for (int nj = 0; nj < 8; nj++) {
            mx0 = fmaxf(mx0, fmaxf(sacc[nj][0], sacc[nj][1]));
            mx1 = fmaxf(mx1, fmaxf(sacc[nj][2], sacc[nj][3]));
        }
        mx0 = fmaxf(mx0, __shfl_xor_sync(0xffffffffu, mx0, 1));
        mx0 = fmaxf(mx0, __shfl_xor_sync(0xffffffffu, mx0, 2));
        mx1 = fmaxf(mx1, __shfl_xor_sync(0xffffffffu, mx1, 1));
        mx1 = fmaxf(mx1, __shfl_xor_sync(0xffffffffu, mx1, 2));
        float mn0 = fmaxf(mi0, mx0), mn1 = fmaxf(mi1, mx1);
        float corr0 = __expf(mi0 - mn0), corr1 = __expf(mi1 - mn1);
        float rs0 = 0.0f, rs1 = 0.0f;
#pragma unroll
        for (int nj = 0; nj < 8; nj++) {
            sacc[nj][0] = __expf(sacc[nj][0] - mn0); rs0 += sacc[nj][0];
            sacc[nj][1] = __expf(sacc[nj][1] - mn0); rs0 += sacc[nj][1];
            sacc[nj][2] = __expf(sacc[nj][2] - mn1); rs1 += sacc[nj][2];
            sacc[nj][3] = __expf(sacc[nj][3] - mn1); rs1 += sacc[nj][3];
        }
        rs0 += __shfl_xor_sync(0xffffffffu, rs0, 1);
        rs0 += __shfl_xor_sync(0xffffffffu, rs0, 2);
        rs1 += __shfl_xor_sync(0xffffffffu, rs1, 1);
        rs1 += __shfl_xor_sync(0xffffffffu, rs1, 2);
        li0 = li0 * corr0 + rs0; mi0 = mn0;
        li1 = li1 * corr1 + rs1; mi1 = mn1;
#pragma unroll
        for (int nj = 0; nj < 16; nj++) {
            o[nj][0] *= corr0; o[nj][1] *= corr0;
            o[nj][2] *= corr1; o[nj][3] *= corr1;
        }

        // ---- store P hi/lo to smem
        {
            const int pr0 = wid * 16 + gid;
#pragma unroll
            for (int nj = 0; nj < 8; nj++) {
                int col = nj * 8 + tig * 2;
                char* pp0 = sm + POFF + (pr0 * PSTR + col) * 2;
                char* pp1 = sm + POFF + ((pr0 + 8) * PSTR + col) * 2;
                split2h(sacc[nj][0], sacc[nj][1], (__half2*)pp0,
                        (__half2*)(pp0 + PPLANE));
                split2h(sacc[nj][2], sacc[nj][3], (__half2*)pp1,
                        (__half2*)(pp1 + PPLANE));
            }
        }
        __syncthreads();

        // ---- O += (Ph+Pl) Vh; V B-frags via ldmatrix.trans
#pragma unroll
        for (int k16 = 0; k16 < 4; k16++) {
            const int k0j = k16 * 16;
            uint32_t pfh[4], pfl[4];
            uint32_t aaddr = sbase + POFF
                + ((wid * 16 + (lane & 15)) * PSTR + k0j + ((lane >> 4) << 3)) * 2;
            ldsm4(pfh, aaddr);
            ldsm4(pfl, aaddr + PPLANE);
            const int mrow = k0j + (lane & 7) + ((lane >> 4) << 3);
            const int nc8 = ((lane >> 3) & 1) * 8;
#pragma unroll
            for (int p = 0; p < 8; p++) {
                uint32_t vf[4];
                ldsm4t(vf, st + KVPLANE + mrow * (KVSTR * 2) + (p * 16 + nc8) * 2);
#pragma unroll
                for (int q = 0; q < 2; q++) {
                    int nj = p * 2 + q;
                    mma16816(o[nj], pfh, vf[q], vf[q + 2]);
                    mma16816(o[nj], pfl, vf[q], vf[q + 2]);
                }
            }
        }
    }
#undef LOAD_KV

    // ---- epilogue: normalize + fp16 hi/lo split to [b,t,d]
    const float inv0 = 1.0f / li0, inv1 = 1.0f / li1;
    const size_t row0 = (size_t)(b * Tt + q0 + wid * 16 + gid) * Dd + h * DH;
    const size_t row1 = row0 + 8 * Dd;
#pragma unroll
    for (int nj = 0; nj < 16; nj++) {
        int col = nj * 8 + tig * 2;
        split2h(o[nj][0] * inv0, o[nj][1] * inv0,
                (__half2*)(ah + row0 + col), (__half2*)(al + row0 + col));
        split2h(o[nj][2] * inv1, o[nj][3] * inv1,
                (__half2*)(ah + row1 + col), (__half2*)(al + row1 + col));
    }
}

// ---------------- launcher ----------------
extern "C" void kernel_launch(void* const* d_in, const int* in_sizes, int n_in,
                              void* d_out, int out_size) {
    (void)in_sizes; (void)n_in; (void)out_size;
    const float* x   = (const float*)d_in[0];
    const float* l3  = (const float*)d_in[1];
    const float* wq  = (const float*)d_in[2];
    const float* wk  = (const float*)d_in[3];
    const float* wv  = (const float*)d_in[4];
    const float* wo  = (const float*)d_in[5];
    const float* rw1 = (const float*)d_in[6];
    const float* rb1 = (const float*)d_in[7];
    const float* rw2 = (const float*)d_in[8];
    const float* rb2 = (const float*)d_in[9];

    float* out = (float*)d_out;
    float* kh  = out + (size_t)Bb * Tt * Dd;
    float* vh  = kh + (size_t)Bb * Tt * Dd;
    float* lam = vh + (size_t)Bb * Tt * Dd;

    float *pl2, *phdn, *plam;
    cudaGetSymbolAddress((void**)&pl2, g_l2);
    cudaGetSymbolAddress((void**)&phdn, g_hdn);
    cudaGetSymbolAddress((void**)&plam, g_lam);

    __half *xh,*xl,*wqh,*wkh,*wvh,*woh,*rw1h;
    __half *qh,*ql,*fh,*fl,*ah,*al,*khh,*vhh;
    cudaGetSymbolAddress((void**)&xh, g_xh);   cudaGetSymbolAddress((void**)&xl, g_xl);
    cudaGetSymbolAddress((void**)&wqh, g_wqh);
    cudaGetSymbolAddress((void**)&wkh, g_wkh);
    cudaGetSymbolAddress((void**)&wvh, g_wvh);
    cudaGetSymbolAddress((void**)&woh, g_woh);
    cudaGetSymbolAddress((void**)&rw1h, g_rw1h);
    cudaGetSymbolAddress((void**)&qh, g_qh);   cudaGetSymbolAddress((void**)&ql, g_ql);
    cudaGetSymbolAddress((void**)&fh, g_fh);   cudaGetSymbolAddress((void**)&fl, g_fl);
    cudaGetSymbolAddress((void**)&ah, g_ah);   cudaGetSymbolAddress((void**)&al, g_al);
    cudaGetSymbolAddress((void**)&khh, g_khh);
    cudaGetSymbolAddress((void**)&vhh, g_vhh);

    cudaFuncSetAttribute(attn_tc, cudaFuncAttributeMaxDynamicSharedMemorySize, ATTN_SMEM);
    cudaFuncSetAttribute(gemm_tc<0>, cudaFuncAttributeMaxDynamicSharedMemorySize, GSMEM);
    cudaFuncSetAttribute(gemm_tc<1>, cudaFuncAttributeMaxDynamicSharedMemorySize, GSMEM);
    cudaFuncSetAttribute(gemm_tc<3>, cudaFuncAttributeMaxDynamicSharedMemorySize, GSMEM);
    cudaFuncSetAttribute(gemm_tc<5>, cudaFuncAttributeMaxDynamicSharedMemorySize, GSMEM);

    const int NBIG4 = (MTOT * Dd) / 4;
    // 1. EMA scan + fused x hi/lo split
    ema_kernel<<<256, 256>>>(x, pl2, xh, xl);
    // 2. weight fp16 conversions
    CvtArgs ca;
    ca.s[0] = wq;  ca.h[0] = wqh;
    ca.s[1] = wk;  ca.h[1] = wkh;
    ca.s[2] = wv;  ca.h[2] = wvh;
    ca.s[3] = wo;  ca.h[3] = woh;
    cvt4_kernel<<<dim3((NBIG4 + 255) / 256, 4), 256>>>(ca, NBIG4);
    cvt_kernel<<<(NBIG4 / 2 + 255) / 256, 256>>>(rw1, rw1h, NBIG4 / 2);
    // 3. q hi/lo = x @ wq^T
    gemm_tc<3><<<dim3(16, 16), 256, GSMEM>>>(xh, xl, wqh, nullptr, nullptr,
                                             nullptr, nullptr, qh, nullptr, ql, Dd, Dd);
    // 4. hdn = silu(q @ rw1^T + rb1)
    gemm_tc<1><<<dim3(8, 16), 256, GSMEM>>>(qh, ql, rw1h, nullptr, rb1,
                                            phdn, nullptr, nullptr, nullptr, nullptr, DHALF, Dd);
    // 5. lam = softmax(hdn @ rw2^T + rb2)
    router_kernel<<<MTOT, 128>>>(phdn, rw2, rb2, plam, lam);
    // 6. fused mix -> fp16 hi/lo
    fuse_kernel<<<(Bb * Tt * Dd / 4 + 255) / 256, 256>>>(x, pl2, l3, plam, fh, fl);
    // 7. kh/vh = heads(fused @ w^T) — ONE fused launch, z selects wk/wv
    gemm_tc<5><<<dim3(16, 16, 2), 256, GSMEM>>>(fh, fl, wkh, wvh, nullptr,
                                                kh, vh, khh, vhh, nullptr, Dd, Dd);
    // 8. HMMA causal flash attention -> fp16 hi/lo
    attn_tc<<<dim3(8, 32), 256, ATTN_SMEM>>>(qh, ql, khh, vhh, ah, al);
    // 9. out = attn @ wo^T
    gemm_tc<0><<<dim3(16, 16), 256, GSMEM>>>(ah, al, woh, nullptr, nullptr,
                                             out, nullptr, nullptr, nullptr, nullptr, Dd, Dd);
}

// round 15
// speedup vs baseline: 5.4534x; 1.0088x over previous
#include <cuda_runtime.h>
#include <cuda_fp16.h>
#include <math.h>
#include <cstdint>

// Problem constants (fixed shapes)
#define Bb 2
#define Tt 1024
#define Dd 2048
#define Hh 16
#define DH 128
#define MTOT (Bb*Tt)      // 2048
#define DHALF (Dd/2)      // 1024

// ================= helpers (baseline PTX only — no 'a'-suffix features) =================
__device__ __forceinline__ uint32_t smem_to_u32(const void* p) {
    uint32_t a;
    asm("{ .reg .u64 t; cvta.to.shared.u64 t, %1; cvt.u32.u64 %0, t; }" : "=r"(a) : "l"(p));
    return a;
}
__device__ __forceinline__ void ldsm4(uint32_t* r, uint32_t addr) {
    asm volatile("ldmatrix.sync.aligned.m8n8.x4.shared.b16 {%0,%1,%2,%3}, [%4];"
        : "=r"(r[0]), "=r"(r[1]), "=r"(r[2]), "=r"(r[3]) : "r"(addr));
}
__device__ __forceinline__ void ldsm4t(uint32_t* r, uint32_t addr) {
    asm volatile("ldmatrix.sync.aligned.m8n8.x4.trans.shared.b16 {%0,%1,%2,%3}, [%4];"
        : "=r"(r[0]), "=r"(r[1]), "=r"(r[2]), "=r"(r[3]) : "r"(addr));
}
// NOTE: non-volatile — register-only effects; lets ptxas schedule/interleave MMAs.
__device__ __forceinline__ void mma16816(float* c, const uint32_t* a, uint32_t b0, uint32_t b1) {
    asm("mma.sync.aligned.m16n8k16.row.col.f32.f16.f16.f32 "
        "{%0,%1,%2,%3}, {%4,%5,%6,%7}, {%8,%9}, {%0,%1,%2,%3};"
        : "+f"(c[0]), "+f"(c[1]), "+f"(c[2]), "+f"(c[3])
        : "r"(a[0]), "r"(a[1]), "r"(a[2]), "r"(a[3]), "r"(b0), "r"(b1));
}
#define CP_ASYNC16(sa, gp) \
    asm volatile("cp.async.cg.shared.global [%0], [%1], 16;" :: "r"(sa), "l"(gp))
#define CP_COMMIT() asm volatile("cp.async.commit_group;" ::: "memory")
#define CP_WAIT1()  asm volatile("cp.async.wait_group 1;" ::: "memory")
#define CP_WAIT0()  asm volatile("cp.async.wait_group 0;" ::: "memory")

// ---------------- scratch (static device globals; no allocation) ----------------
__device__ float g_l2[MTOT*Dd];
__device__ float g_hdn[MTOT*DHALF];
__device__ float g_lam[MTOT*3];

// fp16 buffers: activations hi/lo, weights hi only
__device__ __half g_xh[MTOT*Dd],   g_xl[MTOT*Dd];
__device__ __half g_wqh[Dd*Dd];
__device__ __half g_wkh[Dd*Dd];
__device__ __half g_wvh[Dd*Dd];
__device__ __half g_woh[Dd*Dd];
__device__ __half g_rw1h[DHALF*Dd];
__device__ __half g_qh[MTOT*Dd],   g_ql[MTOT*Dd];
__device__ __half g_fh[MTOT*Dd],   g_fl[MTOT*Dd];
__device__ __half g_ah[MTOT*Dd],   g_al[MTOT*Dd];
__device__ __half g_khh[MTOT*Dd];   // [b,h,t,dh] fp16
__device__ __half g_vhh[MTOT*Dd];

// ---------------- fp32 -> fp16 hi/lo split helpers ----------------
__device__ __forceinline__ void split2h(float a, float b, __half2* hi, __half2* lo) {
    __half h0 = __float2half(a), h1 = __float2half(b);
    *hi = __halves2half2(h0, h1);
    *lo = __halves2half2(__float2half(a - __half2float(h0)),
                         __float2half(b - __half2float(h1)));
}

// 4 equally-sized weight fp32->fp16 conversions in one launch
struct CvtArgs { const float* s[4]; __half* h[4]; };
__global__ void cvt4_kernel(CvtArgs args, int n4) {
    int i = blockIdx.x * blockDim.x + threadIdx.x;
    if (i >= n4) return;
    int z = blockIdx.y;
    float4 v = ((const float4*)args.s[z])[i];
    ((__half2*)args.h[z])[2*i]   = __floats2half2_rn(v.x, v.y);
    ((__half2*)args.h[z])[2*i+1] = __floats2half2_rn(v.z, v.w);
}
__global__ void cvt_kernel(const float* __restrict__ s, __half* __restrict__ h, int n4) {
    int i = blockIdx.x * blockDim.x + threadIdx.x;
    if (i >= n4) return;
    float4 v = ((const float4*)s)[i];
    ((__half2*)h)[2*i]   = __floats2half2_rn(v.x, v.y);
    ((__half2*)h)[2*i+1] = __floats2half2_rn(v.z, v.w);
}

// ---------------- parallel chunked EMA scan + fused x hi/lo split ----------------
__global__ void __launch_bounds__(256)
ema_kernel(const float* __restrict__ x, float* __restrict__ l2,
           __half* __restrict__ xh, __half* __restrict__ xl) {
    const float P64 = 0.0011790184577738583f;   // 0.9^64
    int tid = threadIdx.x;
    int ci = tid & 15, k = tid >> 4;
    int b = blockIdx.x >> 7;
    int c = ((blockIdx.x & 127) << 4) + ci;
    const float* xp = x + (size_t)b * Tt * Dd + c;
    float* lp = l2 + (size_t)b * Tt * Dd + c;
    __half* xhp = xh + (size_t)b * Tt * Dd + c;
    __half* xlp = xl + (size_t)b * Tt * Dd + c;
    const int t0 = k * 64;

    float s = 0.0f;
#pragma unroll 4
    for (int i = 0; i < 64; i++)
        s = 0.9f * s + 0.1f * xp[(size_t)(t0 + i) * Dd];

    __shared__ float endv[16][17], car[16][17];
    endv[k][ci] = s;
    __syncthreads();
    if (k == 0) {
        float carry = 0.0f;
#pragma unroll
        for (int kk = 0; kk < 16; kk++) {
            car[kk][ci] = carry;
            carry = P64 * carry + endv[kk][ci];
        }
    }
    __syncthreads();

    s = car[k][ci];
#pragma unroll 4
    for (int i = 0; i < 64; i++) {
        float xv = xp[(size_t)(t0 + i) * Dd];
        s = 0.9f * s + 0.1f * xv;
        lp[(size_t)(t0 + i) * Dd] = s;
        __half h = __float2half(xv);
        xhp[(size_t)(t0 + i) * Dd] = h;
        xlp[(size_t)(t0 + i) * Dd] = __float2half(xv - __half2float(h));
    }
}

// ================= HMMA fp16 2-pass GEMM =================
// C[M,N] = A[M,K]*B[N,K]^T, D = (Ah+Al)*Bh, fp32 accum.
// CTA 128x128, BK=64, warp grid 4(m)x2(n), warp tile 32x64.
// MMA issue order: all 8 hi-pass (distinct accs), then all 8 lo-pass —
// same-acc reuse distance 8 hides HMMA latency. Per-acc order unchanged.
#define GBK 64
#define GSTR 144
#define GTILEB (128 * GSTR)           // 18432
#define GSTAGE (3 * GTILEB)           // 55296 (Ah, Al, Bh)
#define GSMEM  (2 * GSTAGE)           // 110592

template <int EPI>
__global__ void __launch_bounds__(256, 2)
gemm_tc(const __half* __restrict__ Ah, const __half* __restrict__ Al,
        const __half* __restrict__ Bh, const __half* __restrict__ Bh2,
        const float* __restrict__ bias, float* __restrict__ C, float* __restrict__ C2,
        __half* __restrict__ Chi, __half* __restrict__ Chi2, __half* __restrict__ Clo,
        int N, int K) {
    extern __shared__ char smem[];
    const uint32_t sbase = smem_to_u32(smem);
    const int tid = threadIdx.x;
    const int wid = tid >> 5, lane = tid & 31;
    const int wm = wid & 3, wn = wid >> 2;       // 4(m) x 2(n)
    const int gid = lane >> 2, tig = lane & 3;
    const int m0 = blockIdx.y * 128, n0 = blockIdx.x * 128;

    const __half* Bsel = (EPI == 5 && blockIdx.z) ? Bh2 : Bh;
    float* Csel = (EPI == 5 && blockIdx.z) ? C2 : C;
    __half* Chisel = (EPI == 5 && blockIdx.z) ? Chi2 : Chi;

    const __half* base[3] = {
        Ah + (size_t)m0 * K, Al + (size_t)m0 * K, Bsel + (size_t)n0 * K };

    float acc[2][8][4];
#pragma unroll
    for (int mi = 0; mi < 2; mi++)
#pragma unroll
        for (int nj = 0; nj < 8; nj++)
#pragma unroll
            for (int r = 0; r < 4; r++) acc[mi][nj][r] = 0.0f;

    const int NC = K / GBK;

#define LOAD_CHUNK(cc, ss) do { \
        int _c = (cc), _s = (ss); \
_Pragma("unroll") \
        for (int it = 0; it < 12; it++) { \
            int idx = tid + it * 256; \
            int tile = idx >> 10, row = (idx >> 3) & 127, ch = idx & 7; \
            const __half* gp = base[tile] + (size_t)row * K + _c * GBK + ch * 8; \
            uint32_t sa = sbase + _s * GSTAGE + tile * GTILEB + row * GSTR + ch * 16; \
            CP_ASYNC16(sa, gp); \
        } \
    } while (0)

    LOAD_CHUNK(0, 0); CP_COMMIT();

    const int lrow = lane & 15;
    const int lk8  = (lane >> 4) << 3;

    for (int c = 0; c < NC; c++) {
        if (c + 1 < NC) { LOAD_CHUNK(c + 1, (c + 1) & 1); CP_COMMIT(); CP_WAIT1(); }
        else            { CP_WAIT0(); }
        __syncthreads();
        const uint32_t st = sbase + (c & 1) * GSTAGE;
#pragma unroll
        for (int k16 = 0; k16 < 4; k16++) {
            const int k0 = k16 * 16;
            uint32_t bf[4][4];
#pragma unroll
            for (int p = 0; p < 4; p++) {
                int n = wn * 64 + p * 16 + lrow;
                ldsm4(bf[p], st + 2 * GTILEB + n * GSTR + (k0 + lk8) * 2);
            }
#pragma unroll
            for (int mi = 0; mi < 2; mi++) {
                int r = wm * 32 + mi * 16 + lrow;
                uint32_t aa = st + r * GSTR + (k0 + lk8) * 2;
                uint32_t ahf[4], alf[4];
                ldsm4(ahf, aa);
                ldsm4(alf, aa + GTILEB);
                // hi pass over all 8 accumulators, then lo pass
#pragma unroll
                for (int nj = 0; nj < 8; nj++) {
                    const int p = nj >> 1, q = nj & 1;
                    mma16816(acc[mi][nj], ahf, bf[p][q], bf[p][q + 2]);
                }
#pragma unroll
                for (int nj = 0; nj < 8; nj++) {
                    const int p = nj >> 1, q = nj & 1;
                    mma16816(acc[mi][nj], alf, bf[p][q], bf[p][q + 2]);
                }
            }
        }
        __syncthreads();
    }
#undef LOAD_CHUNK

    // -------- epilogue --------
#pragma unroll
    for (int mi = 0; mi < 2; mi++) {
#pragma unroll
        for (int nj = 0; nj < 8; nj++) {
            const int colw = wn * 64 + nj * 8 + tig * 2;
#pragma unroll
            for (int half = 0; half < 2; half++) {
                const int m = m0 + wm * 32 + mi * 16 + gid + half * 8;
                float v0 = acc[mi][nj][half * 2 + 0];
                float v1 = acc[mi][nj][half * 2 + 1];
                if (EPI == 1) {
                    v0 += bias[n0 + colw];
                    v1 += bias[n0 + colw + 1];
                    v0 = v0 / (1.0f + __expf(-v0));
                    v1 = v1 / (1.0f + __expf(-v1));
                }
                if (EPI == 5) {
                    const int bb = m >> 10, t = m & 1023, h = n0 >> 7;
                    size_t off = ((size_t)(bb * Hh + h) * Tt + t) * DH + colw;
                    *(float2*)(Csel + off) = make_float2(v0, v1);
                    *(__half2*)(Chisel + off) = __floats2half2_rn(v0, v1);
                } else if (EPI == 3) {
                    size_t off = (size_t)m * N + n0 + colw;
                    split2h(v0, v1, (__half2*)(Chi + off), (__half2*)(Clo + off));
                } else {
                    float* cp = Csel + (size_t)m * N + n0 + colw;
                    *(float2*)cp = make_float2(v0, v1);
                }
            }
        }
    }
}

// ---------------- router head ----------------
__global__ void router_kernel(const float* __restrict__ hdn, const float* __restrict__ rw2,
                              const float* __restrict__ rb2, float* __restrict__ lamA,
                              float* __restrict__ lamB) {
    int m = blockIdx.x;
    int tid = threadIdx.x;
    const float* hp = hdn + (size_t)m * DHALF;
    float p0 = 0.f, p1 = 0.f, p2 = 0.f;
    for (int k = tid; k < DHALF; k += 128) {
        float hv = hp[k];
        p0 = fmaf(hv, rw2[k], p0);
        p1 = fmaf(hv, rw2[DHALF + k], p1);
        p2 = fmaf(hv, rw2[2 * DHALF + k], p2);
    }
#pragma unroll
    for (int off = 16; off; off >>= 1) {
        p0 += __shfl_xor_sync(0xffffffffu, p0, off);
        p1 += __shfl_xor_sync(0xffffffffu, p1, off);
        p2 += __shfl_xor_sync(0xffffffffu, p2, off);
    }
    __shared__ float sbm[3][4];
    if ((tid & 31) == 0) {
        int w = tid >> 5;
        sbm[0][w] = p0; sbm[1][w] = p1; sbm[2][w] = p2;
    }
    __syncthreads();
    if (tid == 0) {
        float l0 = sbm[0][0] + sbm[0][1] + sbm[0][2] + sbm[0][3] + rb2[0];
        float l1 = sbm[1][0] + sbm[1][1] + sbm[1][2] + sbm[1][3] + rb2[1];
        float l2 = sbm[2][0] + sbm[2][1] + sbm[2][2] + sbm[2][3] + rb2[2];
        float mx = fmaxf(l0, fmaxf(l1, l2));
        float e0 = __expf(l0 - mx), e1 = __expf(l1 - mx), e2 = __expf(l2 - mx);
        float inv = 1.0f / (e0 + e1 + e2);
        float v0 = e0 * inv, v1 = e1 * inv, v2 = e2 * inv;
        lamA[m * 3 + 0] = v0; lamA[m * 3 + 1] = v1; lamA[m * 3 + 2] = v2;
        lamB[m * 3 + 0] = v0; lamB[m * 3 + 1] = v1; lamB[m * 3 + 2] = v2;
    }
}

// ---------------- fused = lam0*x + lam1*l2 + lam2*l3 -> fp16 hi/lo ----------------
__global__ void fuse_kernel(const float* __restrict__ x, const float* __restrict__ l2,
                            const float* __restrict__ l3, const float* __restrict__ lam,
                            __half* __restrict__ fh, __half* __restrict__ fl) {
    int idx = blockIdx.x * blockDim.x + threadIdx.x;
    if (idx >= Bb * Tt * Dd / 4) return;
    int m = idx / (Dd / 4);
    int c = (idx - m * (Dd / 4)) * 4;
    int b = m >> 10;
    const float* lp = lam + (size_t)m * 3;
    float a0 = lp[0], a1 = lp[1], a2 = lp[2];
    float4 xv = *(const float4*)(x + (size_t)m * Dd + c);
    float4 l2v = *(const float4*)(l2 + (size_t)m * Dd + c);
    float4 l3v = *(const float4*)(l3 + (size_t)b * Dd + c);
    float r0 = a0 * xv.x + a1 * l2v.x + a2 * l3v.x;
    float r1 = a0 * xv.y + a1 * l2v.y + a2 * l3v.y;
    float r2 = a0 * xv.z + a1 * l2v.z + a2 * l3v.z;
    float r3 = a0 * xv.w + a1 * l2v.w + a2 * l3v.w;
    size_t off = (size_t)m * Dd + c;
    split2h(r0, r1, (__half2*)(fh + off),     (__half2*)(fl + off));
    split2h(r2, r3, (__half2*)(fh + off) + 1, (__half2*)(fl + off) + 1);
}

// ================= HMMA flash attention (causal), fp16 2-pass =================
// CTA: 128 q-rows, 8 warps, j-blocks of 64. S=(Qh+Ql)Kh, O=(Ph+Pl)Vh.
// MMA issue order batched: fragments in pairs, hi-block then lo-block (chain dist 4).
#define KVSTR 136
#define KVPLANE (64 * KVSTR * 2)          // 17408
#define KVSTAGE (2 * KVPLANE)             // 34816 (Kh, Vh)
#define PSTR 72
#define PPLANE (128 * PSTR * 2)           // 18432
#define POFF (2 * KVSTAGE)                // 69632
#define ATTN_SMEM (2 * KVSTAGE + 2 * PPLANE)  // 106496

__global__ void __launch_bounds__(256, 1)
attn_tc(const __half* __restrict__ qh, const __half* __restrict__ ql,
        const __half* __restrict__ khh, const __half* __restrict__ vhh,
        __half* __restrict__ ah, __half* __restrict__ al) {
    extern __shared__ char sm[];
    const uint32_t sbase = smem_to_u32(sm);
    const int tid = threadIdx.x;
    const int wid = tid >> 5, lane = tid & 31;
    const int gid = lane >> 2, tig = lane & 3;
    const int qb = 7 - blockIdx.x;            // heavy blocks first
    const int bh = blockIdx.y;
    const int b = bh >> 4, h = bh & 15;
    const int q0 = qb * 128;
    const float scale = 0.08838834764831845f;

    // ---- load Q hi/lo (128x128 fp16 each) into the 2 KV-stage areas
    {
        const __half* qhp = qh + (size_t)(b * Tt + q0) * Dd + h * DH;
        const __half* qlp = ql + (size_t)(b * Tt + q0) * Dd + h * DH;
#pragma unroll
        for (int it = 0; it < 16; it++) {
            int idx = tid + it * 256;
            int plane = idx >> 11;
            int row = (idx >> 4) & 127, ch = idx & 15;
            const __half* gp = (plane ? qlp : qhp) + (size_t)row * Dd + ch * 8;
            uint32_t sa = sbase + plane * KVSTAGE + row * (KVSTR * 2) + ch * 16;
            CP_ASYNC16(sa, gp);
        }
        CP_COMMIT(); CP_WAIT0();
        __syncthreads();
    }
    uint32_t qfh[8][4], qfl[8][4];
    {
        const int m0 = wid * 16;
#pragma unroll
        for (int k16 = 0; k16 < 8; k16++) {
            uint32_t addr = sbase + (m0 + (lane & 15)) * (KVSTR * 2)
                          + (k16 * 16 + ((lane >> 4) << 3)) * 2;
            ldsm4(qfh[k16], addr);
            ldsm4(qfl[k16], addr + KVSTAGE);
        }
    }
    __syncthreads();

    float o[16][4];
#pragma unroll
    for (int nj = 0; nj < 16; nj++)
#pragma unroll
        for (int r = 0; r < 4; r++) o[nj][r] = 0.0f;
    float mi0 = -1e30f, mi1 = -1e30f, li0 = 0.0f, li1 = 0.0f;

    const __half* kb = khh + (size_t)(b * Hh + h) * Tt * DH;
    const __half* vb = vhh + (size_t)(b * Hh + h) * Tt * DH;
    const int njb = 2 * qb + 2;

#define LOAD_KV(jjb, ss) do { \
        int _j0 = (jjb) * 64, _s = (ss); \
_Pragma("unroll") \
        for (int it = 0; it < 8; it++) { \
            int idx = tid + it * 256; \
            int plane = idx >> 10; \
            int row = (idx >> 4) & 63, ch = idx & 15; \
            const __half* gp = (plane ? vb : kb) + (size_t)(_j0 + row) * DH + ch * 8; \
            uint32_t sa = sbase + _s * KVSTAGE + plane * KVPLANE + row * (KVSTR * 2) + ch * 16; \
            CP_ASYNC16(sa, gp); \
        } \
    } while (0)

    LOAD_KV(0, 0); CP_COMMIT();

    for (int jb = 0; jb < njb; jb++) {
        CP_WAIT0();
        __syncthreads();
        if (jb + 1 < njb) { LOAD_KV(jb + 1, (jb + 1) & 1); CP_COMMIT(); }
        const uint32_t st = sbase + (jb & 1) * KVSTAGE;

        // ---- S = (Qh+Ql) Kh, warp computes m16 x n64
        float sacc[8][4];
#pragma unroll
        for (int nj = 0; nj < 8; nj++)
#pragma unroll
            for (int r = 0; r < 4; r++) sacc[nj][r] = 0.0f;

#pragma unroll
        for (int k16 = 0; k16 < 8; k16++) {
            const int k0 = k16 * 16;
#pragma unroll
            for (int pp = 0; pp < 2; pp++) {
                uint32_t kf[2][4];
#pragma unroll
                for (int pi = 0; pi < 2; pi++) {
                    int n = (pp * 2 + pi) * 16 + (lane & 15);
                    ldsm4(kf[pi], st + n * (KVSTR * 2) + (k0 + ((lane >> 4) << 3)) * 2);
                }
                // hi block (4 distinct accs), then lo block
#pragma unroll
                for (int pi = 0; pi < 2; pi++)
#pragma unroll
                    for (int q = 0; q < 2; q++) {
                        int nj = (pp * 2 + pi) * 2 + q;
                        mma16816(sacc[nj], qfh[k16], kf[pi][q], kf[pi][q + 2]);
                    }
#pragma unroll
                for (int pi = 0; pi < 2; pi++)
#pragma unroll
                    for (int q = 0; q < 2; q++) {
                        int nj = (pp * 2 + pi) * 2 + q;
                        mma16816(sacc[nj], qfl[k16], kf[pi][q], kf[pi][q + 2]);
                    }
            }
        }

        // scale + causal mask
#pragma unroll
        for (int nj = 0; nj < 8; nj++)
#pragma unroll
            for (int e = 0; e < 4; e++) sacc[nj][e] *= scale;
        if (jb >= 2 * qb) {
            const int rbase = q0 + wid * 16 + gid;
#pragma unroll
            for (int nj = 0; nj < 8; nj++)
#pragma unroll
                for (int e = 0; e < 4; e++) {
                    int col = jb * 64 + nj * 8 + tig * 2 + (e & 1);
                    int row = rbase + ((e >> 1) << 3);
                    if (col > row) sacc[nj][e] = -1e30f;
                }
        }

        // ---- online softmax
        float mx0 = -1e30f, mx1 = -1e30f;
#pragma unroll
        for (int nj = 0; nj < 8; nj++) {
            mx0 = fmaxf(mx0, fmaxf(sacc[nj][0], sacc[nj][1]));
            mx1 = fmaxf(mx1, fmaxf(sacc[nj][2], sacc[nj][3]));
        }
        mx0 = fmaxf(mx0, __shfl_xor_sync(0xffffffffu, mx0, 1));
        mx0 = fmaxf(mx0, __shfl_xor_sync(0xffffffffu, mx0, 2));
        mx1 = fmaxf(mx1, __shfl_xor_sync(0xffffffffu, mx1, 1));
        mx1 = fmaxf(mx1, __shfl_xor_sync(0xffffffffu, mx1, 2));
        float mn0 = fmaxf(mi0, mx0), mn1 = fmaxf(mi1, mx1);
        float corr0 = __expf(mi0 - mn0), corr1 = __expf(mi1 - mn1);
        float rs0 = 0.0f, rs1 = 0.0f;
#pragma unroll
        for (int nj = 0; nj < 8; nj++) {
            sacc[nj][0] = __expf(sacc[nj][0] - mn0); rs0 += sacc[nj][0];
            sacc[nj][1] = __expf(sacc[nj][1] - mn0); rs0 += sacc[nj][1];
            sacc[nj][2] = __expf(sacc[nj][2] - mn1); rs1 += sacc[nj][2];
            sacc[nj][3] = __expf(sacc[nj][3] - mn1); rs1 += sacc[nj][3];
        }
        rs0 += __shfl_xor_sync(0xffffffffu, rs0, 1);
        rs0 += __shfl_xor_sync(0xffffffffu, rs0, 2);
        rs1 += __shfl_xor_sync(0xffffffffu, rs1, 1);
        rs1 += __shfl_xor_sync(0xffffffffu, rs1, 2);
        li0 = li0 * corr0 + rs0; mi0 = mn0;
        li1 = li1 * corr1 + rs1; mi1 = mn1;
#pragma unroll
        for (int nj = 0; nj < 16; nj++) {
            o[nj][0] *= corr0; o[nj][1] *= corr0;
            o[nj][2] *= corr1; o[nj][3] *= corr1;
        }

        // ---- store P hi/lo to smem
        {
            const int pr0 = wid * 16 + gid;
#pragma unroll
            for (int nj = 0; nj < 8; nj++) {
                int col = nj * 8 + tig * 2;
                char* pp0 = sm + POFF + (pr0 * PSTR + col) * 2;
                char* pp1 = sm + POFF + ((pr0 + 8) * PSTR + col) * 2;
                split2h(sacc[nj][0], sacc[nj][1], (__half2*)pp0,
                        (__half2*)(pp0 + PPLANE));
                split2h(sacc[nj][2], sacc[nj][3], (__half2*)pp1,
                        (__half2*)(pp1 + PPLANE));
            }
        }
        __syncthreads();

        // ---- O += (Ph+Pl) Vh; V B-frags via ldmatrix.trans, pair-batched
#pragma unroll
        for (int k16 = 0; k16 < 4; k16++) {
            const int k0j = k16 * 16;
            uint32_t pfh[4], pfl[4];
            uint32_t aaddr = sbase + POFF
                + ((wid * 16 + (lane & 15)) * PSTR + k0j + ((lane >> 4) << 3)) * 2;
            ldsm4(pfh, aaddr);
            ldsm4(pfl, aaddr + PPLANE);
            const int mrow = k0j + (lane & 7) + ((lane >> 4) << 3);
            const int nc8 = ((lane >> 3) & 1) * 8;
#pragma unroll
            for (int pp = 0; pp < 4; pp++) {
                uint32_t vf[2][4];
#pragma unroll
                for (int pi = 0; pi < 2; pi++) {
                    int p = pp * 2 + pi;
                    ldsm4t(vf[pi], st + KVPLANE + mrow * (KVSTR * 2) + (p * 16 + nc8) * 2);
                }
                // hi block (4 distinct accs), then lo block
#pragma unroll
                for (int pi = 0; pi < 2; pi++)
#pragma unroll
                    for (int q = 0; q < 2; q++) {
                        int nj = (pp * 2 + pi) * 2 + q;
                        mma16816(o[nj], pfh, vf[pi][q], vf[pi][q + 2]);
                    }
#pragma unroll
                for (int pi = 0; pi < 2; pi++)
#pragma unroll
                    for (int q = 0; q < 2; q++) {
                        int nj = (pp * 2 + pi) * 2 + q;
                        mma16816(o[nj], pfl, vf[pi][q], vf[pi][q + 2]);
                    }
            }
        }
    }
#undef LOAD_KV

    // ---- epilogue: normalize + fp16 hi/lo split to [b,t,d]
    const float inv0 = 1.0f / li0, inv1 = 1.0f / li1;
    const size_t row0 = (size_t)(b * Tt + q0 + wid * 16 + gid) * Dd + h * DH;
    const size_t row1 = row0 + 8 * Dd;
#pragma unroll
    for (int nj = 0; nj < 16; nj++) {
        int col = nj * 8 + tig * 2;
        split2h(o[nj][0] * inv0, o[nj][1] * inv0,
                (__half2*)(ah + row0 + col), (__half2*)(al + row0 + col));
        split2h(o[nj][2] * inv1, o[nj][3] * inv1,
                (__half2*)(ah + row1 + col), (__half2*)(al + row1 + col));
    }
}

// ---------------- launcher ----------------
extern "C" void kernel_launch(void* const* d_in, const int* in_sizes, int n_in,
                              void* d_out, int out_size) {
    (void)in_sizes; (void)n_in; (void)out_size;
    const float* x   = (const float*)d_in[0];
    const float* l3  = (const float*)d_in[1];
    const float* wq  = (const float*)d_in[2];
    const float* wk  = (const float*)d_in[3];
    const float* wv  = (const float*)d_in[4];
    const float* wo  = (const float*)d_in[5];
    const float* rw1 = (const float*)d_in[6];
    const float* rb1 = (const float*)d_in[7];
    const float* rw2 = (const float*)d_in[8];
    const float* rb2 = (const float*)d_in[9];

    float* out = (float*)d_out;
    float* kh  = out + (size_t)Bb * Tt * Dd;
    float* vh  = kh + (size_t)Bb * Tt * Dd;
    float* lam = vh + (size_t)Bb * Tt * Dd;

    float *pl2, *phdn, *plam;
    cudaGetSymbolAddress((void**)&pl2, g_l2);
    cudaGetSymbolAddress((void**)&phdn, g_hdn);
    cudaGetSymbolAddress((void**)&plam, g_lam);

    __half *xh,*xl,*wqh,*wkh,*wvh,*woh,*rw1h;
    __half *qh,*ql,*fh,*fl,*ah,*al,*khh,*vhh;
    cudaGetSymbolAddress((void**)&xh, g_xh);   cudaGetSymbolAddress((void**)&xl, g_xl);
    cudaGetSymbolAddress((void**)&wqh, g_wqh);
    cudaGetSymbolAddress((void**)&wkh, g_wkh);
    cudaGetSymbolAddress((void**)&wvh, g_wvh);
    cudaGetSymbolAddress((void**)&woh, g_woh);
    cudaGetSymbolAddress((void**)&rw1h, g_rw1h);
    cudaGetSymbolAddress((void**)&qh, g_qh);   cudaGetSymbolAddress((void**)&ql, g_ql);
    cudaGetSymbolAddress((void**)&fh, g_fh);   cudaGetSymbolAddress((void**)&fl, g_fl);
    cudaGetSymbolAddress((void**)&ah, g_ah);   cudaGetSymbolAddress((void**)&al, g_al);
    cudaGetSymbolAddress((void**)&khh, g_khh);
    cudaGetSymbolAddress((void**)&vhh, g_vhh);

    cudaFuncSetAttribute(attn_tc, cudaFuncAttributeMaxDynamicSharedMemorySize, ATTN_SMEM);
    cudaFuncSetAttribute(gemm_tc<0>, cudaFuncAttributeMaxDynamicSharedMemorySize, GSMEM);
    cudaFuncSetAttribute(gemm_tc<1>, cudaFuncAttributeMaxDynamicSharedMemorySize, GSMEM);
    cudaFuncSetAttribute(gemm_tc<3>, cudaFuncAttributeMaxDynamicSharedMemorySize, GSMEM);
    cudaFuncSetAttribute(gemm_tc<5>, cudaFuncAttributeMaxDynamicSharedMemorySize, GSMEM);

    const int NBIG4 = (MTOT * Dd) / 4;
    // 1. EMA scan + fused x hi/lo split
    ema_kernel<<<256, 256>>>(x, pl2, xh, xl);
    // 2. weight fp16 conversions
    CvtArgs ca;
    ca.s[0] = wq;  ca.h[0] = wqh;
    ca.s[1] = wk;  ca.h[1] = wkh;
    ca.s[2] = wv;  ca.h[2] = wvh;
    ca.s[3] = wo;  ca.h[3] = woh;
    cvt4_kernel<<<dim3((NBIG4 + 255) / 256, 4), 256>>>(ca, NBIG4);
    cvt_kernel<<<(NBIG4 / 2 + 255) / 256, 256>>>(rw1, rw1h, NBIG4 / 2);
    // 3. q hi/lo = x @ wq^T
    gemm_tc<3><<<dim3(16, 16), 256, GSMEM>>>(xh, xl, wqh, nullptr, nullptr,
                                             nullptr, nullptr, qh, nullptr, ql, Dd, Dd);
    // 4. hdn = silu(q @ rw1^T + rb1)
    gemm_tc<1><<<dim3(8, 16), 256, GSMEM>>>(qh, ql, rw1h, nullptr, rb1,
                                            phdn, nullptr, nullptr, nullptr, nullptr, DHALF, Dd);
    // 5. lam = softmax(hdn @ rw2^T + rb2)
    router_kernel<<<MTOT, 128>>>(phdn, rw2, rb2, plam, lam);
    // 6. fused mix -> fp16 hi/lo
    fuse_kernel<<<(Bb * Tt * Dd / 4 + 255) / 256, 256>>>(x, pl2, l3, plam, fh, fl);
    // 7. kh/vh = heads(fused @ w^T) — ONE fused launch, z selects wk/wv
    gemm_tc<5><<<dim3(16, 16, 2), 256, GSMEM>>>(fh, fl, wkh, wvh, nullptr,
                                                kh, vh, khh, vhh, nullptr, Dd, Dd);
    // 8. HMMA causal flash attention -> fp16 hi/lo
    attn_tc<<<dim3(8, 32), 256, ATTN_SMEM>>>(qh, ql, khh, vhh, ah, al);
    // 9. out = attn @ wo^T
    gemm_tc<0><<<dim3(16, 16), 256, GSMEM>>>(ah, al, woh, nullptr, nullptr,
                                             out, nullptr, nullptr, nullptr, nullptr, Dd, Dd);
}